// round 1
// baseline (speedup 1.0000x reference)
#include <cuda_runtime.h>
#include <cuda_bf16.h>
#include <cstddef>

#define NN 50000
#define EE 1600000

// ---------------- scratch (static device globals; no allocation allowed) ----
__device__ __align__(16) float g_support[(size_t)NN * 256];
__device__ __align__(16) float g_x1[(size_t)NN * 256];
__device__ __align__(16) float g_x2[(size_t)NN * 256];
__device__ __align__(16) float g_x3[(size_t)NN * 128];

// ---------------- zero fill -------------------------------------------------
__global__ void zero_kernel(float4* __restrict__ p, int n4) {
    int i = blockIdx.x * blockDim.x + threadIdx.x;
    int stride = gridDim.x * blockDim.x;
    for (; i < n4; i += stride) p[i] = make_float4(0.f, 0.f, 0.f, 0.f);
}

// ---------------- tiled fp32 GEMM: C[M,N] = A[M,K] @ B[K,N] -----------------
// BM=BN=64, BK=16, 256 threads, 4x4 register tile per thread.
// K multiple of 16, N multiple of 64 (holds: K in {512,256}, N in {256,128}).
__global__ __launch_bounds__(256) void sgemm_kernel(
    const float* __restrict__ A, const float* __restrict__ B,
    float* __restrict__ C, int M, int K, int N)
{
    __shared__ float As[16][64];
    __shared__ float Bs[16][64];

    const int t  = threadIdx.x;
    const int m0 = blockIdx.x * 64;
    const int n0 = blockIdx.y * 64;
    const int ty = t >> 4;       // 0..15
    const int tx = t & 15;       // 0..15

    // A-load mapping: 64 rows x 16 cols, one float4 per thread
    const int arow = t >> 2;          // 0..63
    const int acol = (t & 3) * 4;     // 0,4,8,12
    // B-load mapping: 16 rows x 64 cols, one float4 per thread
    const int brow = t >> 4;          // 0..15
    const int bcol = (t & 15) * 4;    // 0..60

    float acc[4][4] = {};

    for (int k0 = 0; k0 < K; k0 += 16) {
        const int gm = m0 + arow;
        float4 av = make_float4(0.f, 0.f, 0.f, 0.f);
        if (gm < M)
            av = *reinterpret_cast<const float4*>(A + (size_t)gm * K + k0 + acol);
        As[acol + 0][arow] = av.x;
        As[acol + 1][arow] = av.y;
        As[acol + 2][arow] = av.z;
        As[acol + 3][arow] = av.w;

        float4 bv = *reinterpret_cast<const float4*>(B + (size_t)(k0 + brow) * N + n0 + bcol);
        *reinterpret_cast<float4*>(&Bs[brow][bcol]) = bv;

        __syncthreads();

#pragma unroll
        for (int kk = 0; kk < 16; kk++) {
            float4 a = *reinterpret_cast<const float4*>(&As[kk][ty * 4]);
            float4 b = *reinterpret_cast<const float4*>(&Bs[kk][tx * 4]);
            float ar[4] = {a.x, a.y, a.z, a.w};
            float br[4] = {b.x, b.y, b.z, b.w};
#pragma unroll
            for (int i = 0; i < 4; i++)
#pragma unroll
                for (int j = 0; j < 4; j++)
                    acc[i][j] = fmaf(ar[i], br[j], acc[i][j]);
        }
        __syncthreads();
    }

#pragma unroll
    for (int i = 0; i < 4; i++) {
        const int gm = m0 + ty * 4 + i;
        if (gm < M) {
            float4 v = make_float4(acc[i][0], acc[i][1], acc[i][2], acc[i][3]);
            *reinterpret_cast<float4*>(C + (size_t)gm * N + n0 + tx * 4) = v;
        }
    }
}

// ---------------- SpMM: out[dst] += w * support[src], warp per edge ---------
// F4 = F/4 (float4 columns). Vectorized float4 atomicAdd (sm_90+).
__global__ __launch_bounds__(256) void spmm_kernel(
    const float4* __restrict__ sup,
    const int* __restrict__ src, const int* __restrict__ dst,
    const float* __restrict__ w,
    float4* __restrict__ out, int E, int F4)
{
    const int gtid = blockIdx.x * blockDim.x + threadIdx.x;
    const int e    = gtid >> 5;
    const int lane = gtid & 31;
    if (e >= E) return;

    const int   s  = src[e];
    const int   d  = dst[e];
    const float we = w[e];

    const float4* __restrict__ srow = sup + (size_t)s * F4;
    float4* __restrict__       drow = out + (size_t)d * F4;

    for (int j = lane; j < F4; j += 32) {
        float4 v = srow[j];
        v.x *= we; v.y *= we; v.z *= we; v.w *= we;
        atomicAdd(drow + j, v);
    }
}

// ---------------- bias (+ optional relu), in place --------------------------
__global__ void bias_act_kernel(float4* __restrict__ x, const float4* __restrict__ b,
                                int n4, int F4, int do_relu)
{
    int i = blockIdx.x * blockDim.x + threadIdx.x;
    int stride = gridDim.x * blockDim.x;
    for (; i < n4; i += stride) {
        float4 v  = x[i];
        float4 bb = b[i % F4];
        v.x += bb.x; v.y += bb.y; v.z += bb.z; v.w += bb.w;
        if (do_relu) {
            v.x = fmaxf(v.x, 0.f); v.y = fmaxf(v.y, 0.f);
            v.z = fmaxf(v.z, 0.f); v.w = fmaxf(v.w, 0.f);
        }
        x[i] = v;
    }
}

// ---------------- head: concat(640) @ linW[640,16] + linb, log_softmax ------
// 16 lanes per node (lane = class). linW staged in shared (40KB).
__global__ __launch_bounds__(256) void head_kernel(
    const float* __restrict__ x1, const float* __restrict__ x2,
    const float* __restrict__ x3,
    const float* __restrict__ linW, const float* __restrict__ linb,
    float* __restrict__ out, int n)
{
    __shared__ float sW[640 * 16];
    for (int i = threadIdx.x; i < 640 * 16; i += blockDim.x) sW[i] = linW[i];
    __syncthreads();

    const int gtid = blockIdx.x * blockDim.x + threadIdx.x;
    const int node = gtid >> 4;
    const int c    = gtid & 15;
    if (node >= n) return;

    const float* __restrict__ r1 = x1 + (size_t)node * 256;
    const float* __restrict__ r2 = x2 + (size_t)node * 256;
    const float* __restrict__ r3 = x3 + (size_t)node * 128;

    float acc = linb[c];
#pragma unroll 4
    for (int k = 0; k < 256; k++) acc = fmaf(r1[k], sW[k * 16 + c], acc);
#pragma unroll 4
    for (int k = 0; k < 256; k++) acc = fmaf(r2[k], sW[(256 + k) * 16 + c], acc);
#pragma unroll 4
    for (int k = 0; k < 128; k++) acc = fmaf(r3[k], sW[(512 + k) * 16 + c], acc);

    // log_softmax over 16 lanes (xor shuffles stay inside each 16-lane half)
    float m = acc;
#pragma unroll
    for (int o = 8; o > 0; o >>= 1)
        m = fmaxf(m, __shfl_xor_sync(0xffffffffu, m, o));
    float ex = expf(acc - m);
    float ssum = ex;
#pragma unroll
    for (int o = 8; o > 0; o >>= 1)
        ssum += __shfl_xor_sync(0xffffffffu, ssum, o);

    out[(size_t)node * 16 + c] = acc - m - logf(ssum);
}

// ---------------- launch ----------------------------------------------------
extern "C" void kernel_launch(void* const* d_in, const int* in_sizes, int n_in,
                              void* d_out, int out_size)
{
    const float* x       = (const float*)d_in[0];
    const float* edge_w  = (const float*)d_in[1];
    const float* W1      = (const float*)d_in[2];
    const float* b1      = (const float*)d_in[3];
    const float* W2      = (const float*)d_in[4];
    const float* b2      = (const float*)d_in[5];
    const float* W3      = (const float*)d_in[6];
    const float* b3      = (const float*)d_in[7];
    const float* linW    = (const float*)d_in[8];
    const float* linb    = (const float*)d_in[9];
    const int*   esrc    = (const int*)d_in[10];
    const int*   edst    = (const int*)d_in[11];
    float*       out     = (float*)d_out;

    static float *sup = nullptr, *x1 = nullptr, *x2 = nullptr, *x3 = nullptr;
    if (!sup) {
        cudaGetSymbolAddress((void**)&sup, g_support);
        cudaGetSymbolAddress((void**)&x1,  g_x1);
        cudaGetSymbolAddress((void**)&x2,  g_x2);
        cudaGetSymbolAddress((void**)&x3,  g_x3);
    }

    const int M = NN, E = EE;
    const int spmm_blocks = (E * 32 + 255) / 256;

    // ---- layer 1: support = x @ W1 ; x1 = relu(spmm + b1) ----
    {
        dim3 grid((M + 63) / 64, 256 / 64);
        sgemm_kernel<<<grid, 256>>>(x, W1, sup, M, 512, 256);
        int n4 = M * 64;
        zero_kernel<<<(n4 + 255) / 256, 256>>>((float4*)x1, n4);
        spmm_kernel<<<spmm_blocks, 256>>>((const float4*)sup, esrc, edst, edge_w,
                                          (float4*)x1, E, 64);
        bias_act_kernel<<<(n4 + 255) / 256, 256>>>((float4*)x1, (const float4*)b1,
                                                   n4, 64, 1);
    }
    // ---- layer 2: support = x1 @ W2 ; x2 = relu(spmm + b2) ----
    {
        dim3 grid((M + 63) / 64, 256 / 64);
        sgemm_kernel<<<grid, 256>>>(x1, W2, sup, M, 256, 256);
        int n4 = M * 64;
        zero_kernel<<<(n4 + 255) / 256, 256>>>((float4*)x2, n4);
        spmm_kernel<<<spmm_blocks, 256>>>((const float4*)sup, esrc, edst, edge_w,
                                          (float4*)x2, E, 64);
        bias_act_kernel<<<(n4 + 255) / 256, 256>>>((float4*)x2, (const float4*)b2,
                                                   n4, 64, 1);
    }
    // ---- layer 3: support = x2 @ W3 ; x3 = spmm + b3 (no relu) ----
    {
        dim3 grid((M + 63) / 64, 128 / 64);
        sgemm_kernel<<<grid, 256>>>(x2, W3, sup, M, 256, 128);
        int n4 = M * 32;
        zero_kernel<<<(n4 + 255) / 256, 256>>>((float4*)x3, n4);
        spmm_kernel<<<spmm_blocks, 256>>>((const float4*)sup, esrc, edst, edge_w,
                                          (float4*)x3, E, 32);
        bias_act_kernel<<<(n4 + 255) / 256, 256>>>((float4*)x3, (const float4*)b3,
                                                   n4, 32, 0);
    }
    // ---- head: logits + log_softmax ----
    head_kernel<<<(M * 16 + 255) / 256, 256>>>(x1, x2, x3, linW, linb, out, M);
}

// round 2
// speedup vs baseline: 1.0060x; 1.0060x over previous
#include <cuda_runtime.h>
#include <cuda_bf16.h>
#include <cstddef>

#define NN 50000
#define EE 1600000

// ---------------- scratch (static device globals; no allocation allowed) ----
__device__ __align__(16) float g_support[(size_t)NN * 256];
__device__ __align__(16) float g_x1[(size_t)NN * 256];
__device__ __align__(16) float g_x2[(size_t)NN * 256];
__device__ __align__(16) float g_x3[(size_t)NN * 128];

// ---------------- zero fill -------------------------------------------------
__global__ void zero_kernel(float4* __restrict__ p, int n4) {
    int i = blockIdx.x * blockDim.x + threadIdx.x;
    int stride = gridDim.x * blockDim.x;
    for (; i < n4; i += stride) p[i] = make_float4(0.f, 0.f, 0.f, 0.f);
}

// ---------------- tiled fp32 GEMM: C[M,N] = A[M,K] @ B[K,N] -----------------
// BM=BN=64, BK=16, 256 threads, 4x4 register tile per thread.
// K multiple of 16, N multiple of 64 (holds: K in {512,256}, N in {256,128}).
__global__ __launch_bounds__(256) void sgemm_kernel(
    const float* __restrict__ A, const float* __restrict__ B,
    float* __restrict__ C, int M, int K, int N)
{
    __shared__ float As[16][64];
    __shared__ float Bs[16][64];

    const int t  = threadIdx.x;
    const int m0 = blockIdx.x * 64;
    const int n0 = blockIdx.y * 64;
    const int ty = t >> 4;       // 0..15
    const int tx = t & 15;       // 0..15

    // A-load mapping: 64 rows x 16 cols, one float4 per thread
    const int arow = t >> 2;          // 0..63
    const int acol = (t & 3) * 4;     // 0,4,8,12
    // B-load mapping: 16 rows x 64 cols, one float4 per thread
    const int brow = t >> 4;          // 0..15
    const int bcol = (t & 15) * 4;    // 0..60

    float acc[4][4] = {};

    for (int k0 = 0; k0 < K; k0 += 16) {
        const int gm = m0 + arow;
        float4 av = make_float4(0.f, 0.f, 0.f, 0.f);
        if (gm < M)
            av = *reinterpret_cast<const float4*>(A + (size_t)gm * K + k0 + acol);
        As[acol + 0][arow] = av.x;
        As[acol + 1][arow] = av.y;
        As[acol + 2][arow] = av.z;
        As[acol + 3][arow] = av.w;

        float4 bv = *reinterpret_cast<const float4*>(B + (size_t)(k0 + brow) * N + n0 + bcol);
        *reinterpret_cast<float4*>(&Bs[brow][bcol]) = bv;

        __syncthreads();

#pragma unroll
        for (int kk = 0; kk < 16; kk++) {
            float4 a = *reinterpret_cast<const float4*>(&As[kk][ty * 4]);
            float4 b = *reinterpret_cast<const float4*>(&Bs[kk][tx * 4]);
            float ar[4] = {a.x, a.y, a.z, a.w};
            float br[4] = {b.x, b.y, b.z, b.w};
#pragma unroll
            for (int i = 0; i < 4; i++)
#pragma unroll
                for (int j = 0; j < 4; j++)
                    acc[i][j] = fmaf(ar[i], br[j], acc[i][j]);
        }
        __syncthreads();
    }

#pragma unroll
    for (int i = 0; i < 4; i++) {
        const int gm = m0 + ty * 4 + i;
        if (gm < M) {
            float4 v = make_float4(acc[i][0], acc[i][1], acc[i][2], acc[i][3]);
            *reinterpret_cast<float4*>(C + (size_t)gm * N + n0 + tx * 4) = v;
        }
    }
}

// ---------------- SpMM: out[dst] += w * support[src], warp per edge ---------
// F4 = F/4 (float4 columns). Vectorized float4 atomicAdd (sm_90+).
__global__ __launch_bounds__(256) void spmm_kernel(
    const float4* __restrict__ sup,
    const int* __restrict__ src, const int* __restrict__ dst,
    const float* __restrict__ w,
    float4* __restrict__ out, int E, int F4)
{
    const int gtid = blockIdx.x * blockDim.x + threadIdx.x;
    const int e    = gtid >> 5;
    const int lane = gtid & 31;
    if (e >= E) return;

    const int   s  = src[e];
    const int   d  = dst[e];
    const float we = w[e];

    const float4* __restrict__ srow = sup + (size_t)s * F4;
    float4* __restrict__       drow = out + (size_t)d * F4;

    for (int j = lane; j < F4; j += 32) {
        float4 v = srow[j];
        v.x *= we; v.y *= we; v.z *= we; v.w *= we;
        atomicAdd(drow + j, v);
    }
}

// ---------------- bias (+ optional relu), in place --------------------------
__global__ void bias_act_kernel(float4* __restrict__ x, const float4* __restrict__ b,
                                int n4, int F4, int do_relu)
{
    int i = blockIdx.x * blockDim.x + threadIdx.x;
    int stride = gridDim.x * blockDim.x;
    for (; i < n4; i += stride) {
        float4 v  = x[i];
        float4 bb = b[i % F4];
        v.x += bb.x; v.y += bb.y; v.z += bb.z; v.w += bb.w;
        if (do_relu) {
            v.x = fmaxf(v.x, 0.f); v.y = fmaxf(v.y, 0.f);
            v.z = fmaxf(v.z, 0.f); v.w = fmaxf(v.w, 0.f);
        }
        x[i] = v;
    }
}

// ---------------- head: concat(640) @ linW[640,16] + linb, log_softmax ------
// 16 lanes per node (lane = class). linW staged in shared (40KB).
__global__ __launch_bounds__(256) void head_kernel(
    const float* __restrict__ x1, const float* __restrict__ x2,
    const float* __restrict__ x3,
    const float* __restrict__ linW, const float* __restrict__ linb,
    float* __restrict__ out, int n)
{
    __shared__ float sW[640 * 16];
    for (int i = threadIdx.x; i < 640 * 16; i += blockDim.x) sW[i] = linW[i];
    __syncthreads();

    const int gtid = blockIdx.x * blockDim.x + threadIdx.x;
    const int node = gtid >> 4;
    const int c    = gtid & 15;
    if (node >= n) return;

    const float* __restrict__ r1 = x1 + (size_t)node * 256;
    const float* __restrict__ r2 = x2 + (size_t)node * 256;
    const float* __restrict__ r3 = x3 + (size_t)node * 128;

    float acc = linb[c];
#pragma unroll 4
    for (int k = 0; k < 256; k++) acc = fmaf(r1[k], sW[k * 16 + c], acc);
#pragma unroll 4
    for (int k = 0; k < 256; k++) acc = fmaf(r2[k], sW[(256 + k) * 16 + c], acc);
#pragma unroll 4
    for (int k = 0; k < 128; k++) acc = fmaf(r3[k], sW[(512 + k) * 16 + c], acc);

    // log_softmax over 16 lanes (xor shuffles stay inside each 16-lane half)
    float m = acc;
#pragma unroll
    for (int o = 8; o > 0; o >>= 1)
        m = fmaxf(m, __shfl_xor_sync(0xffffffffu, m, o));
    float ex = expf(acc - m);
    float ssum = ex;
#pragma unroll
    for (int o = 8; o > 0; o >>= 1)
        ssum += __shfl_xor_sync(0xffffffffu, ssum, o);

    out[(size_t)node * 16 + c] = acc - m - logf(ssum);
}

// ---------------- launch ----------------------------------------------------
extern "C" void kernel_launch(void* const* d_in, const int* in_sizes, int n_in,
                              void* d_out, int out_size)
{
    const float* x       = (const float*)d_in[0];
    const float* edge_w  = (const float*)d_in[1];
    const float* W1      = (const float*)d_in[2];
    const float* b1      = (const float*)d_in[3];
    const float* W2      = (const float*)d_in[4];
    const float* b2      = (const float*)d_in[5];
    const float* W3      = (const float*)d_in[6];
    const float* b3      = (const float*)d_in[7];
    const float* linW    = (const float*)d_in[8];
    const float* linb    = (const float*)d_in[9];
    const int*   esrc    = (const int*)d_in[10];
    const int*   edst    = (const int*)d_in[11];
    float*       out     = (float*)d_out;

    static float *sup = nullptr, *x1 = nullptr, *x2 = nullptr, *x3 = nullptr;
    if (!sup) {
        cudaGetSymbolAddress((void**)&sup, g_support);
        cudaGetSymbolAddress((void**)&x1,  g_x1);
        cudaGetSymbolAddress((void**)&x2,  g_x2);
        cudaGetSymbolAddress((void**)&x3,  g_x3);
    }

    const int M = NN, E = EE;
    const int spmm_blocks = (E * 32 + 255) / 256;

    // ---- layer 1: support = x @ W1 ; x1 = relu(spmm + b1) ----
    {
        dim3 grid((M + 63) / 64, 256 / 64);
        sgemm_kernel<<<grid, 256>>>(x, W1, sup, M, 512, 256);
        int n4 = M * 64;
        zero_kernel<<<(n4 + 255) / 256, 256>>>((float4*)x1, n4);
        spmm_kernel<<<spmm_blocks, 256>>>((const float4*)sup, esrc, edst, edge_w,
                                          (float4*)x1, E, 64);
        bias_act_kernel<<<(n4 + 255) / 256, 256>>>((float4*)x1, (const float4*)b1,
                                                   n4, 64, 1);
    }
    // ---- layer 2: support = x1 @ W2 ; x2 = relu(spmm + b2) ----
    {
        dim3 grid((M + 63) / 64, 256 / 64);
        sgemm_kernel<<<grid, 256>>>(x1, W2, sup, M, 256, 256);
        int n4 = M * 64;
        zero_kernel<<<(n4 + 255) / 256, 256>>>((float4*)x2, n4);
        spmm_kernel<<<spmm_blocks, 256>>>((const float4*)sup, esrc, edst, edge_w,
                                          (float4*)x2, E, 64);
        bias_act_kernel<<<(n4 + 255) / 256, 256>>>((float4*)x2, (const float4*)b2,
                                                   n4, 64, 1);
    }
    // ---- layer 3: support = x2 @ W3 ; x3 = spmm + b3 (no relu) ----
    {
        dim3 grid((M + 63) / 64, 128 / 64);
        sgemm_kernel<<<grid, 256>>>(x2, W3, sup, M, 256, 128);
        int n4 = M * 32;
        zero_kernel<<<(n4 + 255) / 256, 256>>>((float4*)x3, n4);
        spmm_kernel<<<spmm_blocks, 256>>>((const float4*)sup, esrc, edst, edge_w,
                                          (float4*)x3, E, 32);
        bias_act_kernel<<<(n4 + 255) / 256, 256>>>((float4*)x3, (const float4*)b3,
                                                   n4, 32, 0);
    }
    // ---- head: logits + log_softmax ----
    head_kernel<<<(M * 16 + 255) / 256, 256>>>(x1, x2, x3, linW, linb, out, M);
}

// round 4
// speedup vs baseline: 1.6117x; 1.6021x over previous
#include <cuda_runtime.h>
#include <cuda_bf16.h>
#include <cstddef>

#define NN 50000
#define EE 1600000

// ---------------- scratch (static device globals; no allocation allowed) ----
__device__ __align__(16) float g_support[(size_t)NN * 256];
__device__ __align__(16) float g_x1[(size_t)NN * 256];
__device__ __align__(16) float g_x2[(size_t)NN * 256];
__device__ __align__(16) float g_x3[(size_t)NN * 128];

// CSR-by-destination scratch
__device__ int   g_deg[NN];
__device__ int   g_cursor[NN];
__device__ int   g_row_ptr[NN + 1];
__device__ int   g_csr_src[EE];
__device__ float g_csr_w[EE];

// ---------------- CSR build -------------------------------------------------
__global__ void zero_int2_kernel(int* __restrict__ a, int* __restrict__ b, int n) {
    int i = blockIdx.x * blockDim.x + threadIdx.x;
    if (i < n) { a[i] = 0; b[i] = 0; }
}

__global__ void degree_kernel(const int* __restrict__ dst, int* __restrict__ deg, int E) {
    int e = blockIdx.x * blockDim.x + threadIdx.x;
    if (e < E) atomicAdd(&deg[dst[e]], 1);
}

// Single-block exclusive scan over n=NN elements -> row_ptr[0..n]
__global__ __launch_bounds__(1024) void scan_kernel(
    const int* __restrict__ deg, int* __restrict__ row_ptr, int n)
{
    __shared__ int ssum[1024];
    const int t  = threadIdx.x;
    const int CH = (n + 1023) / 1024;
    const int base = t * CH;

    int local = 0;
    for (int i = 0; i < CH; i++) {
        int idx = base + i;
        if (idx < n) local += deg[idx];
    }
    ssum[t] = local;
    __syncthreads();

    // inclusive Hillis-Steele scan of per-thread sums
    for (int off = 1; off < 1024; off <<= 1) {
        int add = (t >= off) ? ssum[t - off] : 0;
        __syncthreads();
        ssum[t] += add;
        __syncthreads();
    }

    int run = (t == 0) ? 0 : ssum[t - 1];
    for (int i = 0; i < CH; i++) {
        int idx = base + i;
        if (idx < n) { row_ptr[idx] = run; run += deg[idx]; }
    }
    if (t == 0) row_ptr[n] = ssum[1023];
}

__global__ void scatter_kernel(
    const int* __restrict__ src, const int* __restrict__ dst,
    const float* __restrict__ w,
    const int* __restrict__ row_ptr, int* __restrict__ cursor,
    int* __restrict__ csr_src, float* __restrict__ csr_w, int E)
{
    int e = blockIdx.x * blockDim.x + threadIdx.x;
    if (e >= E) return;
    int d   = dst[e];
    int pos = atomicAdd(&cursor[d], 1);
    int idx = row_ptr[d] + pos;
    csr_src[idx] = src[e];
    csr_w[idx]   = w[e];
}

// ---------------- tiled fp32 GEMM: C[M,N] = A[M,K] @ B[K,N] -----------------
__global__ __launch_bounds__(256) void sgemm_kernel(
    const float* __restrict__ A, const float* __restrict__ B,
    float* __restrict__ C, int M, int K, int N)
{
    __shared__ float As[16][64];
    __shared__ float Bs[16][64];

    const int t  = threadIdx.x;
    const int m0 = blockIdx.x * 64;
    const int n0 = blockIdx.y * 64;
    const int ty = t >> 4;
    const int tx = t & 15;

    const int arow = t >> 2;
    const int acol = (t & 3) * 4;
    const int brow = t >> 4;
    const int bcol = (t & 15) * 4;

    float acc[4][4] = {};

    for (int k0 = 0; k0 < K; k0 += 16) {
        const int gm = m0 + arow;
        float4 av = make_float4(0.f, 0.f, 0.f, 0.f);
        if (gm < M)
            av = *reinterpret_cast<const float4*>(A + (size_t)gm * K + k0 + acol);
        As[acol + 0][arow] = av.x;
        As[acol + 1][arow] = av.y;
        As[acol + 2][arow] = av.z;
        As[acol + 3][arow] = av.w;

        float4 bv = *reinterpret_cast<const float4*>(B + (size_t)(k0 + brow) * N + n0 + bcol);
        *reinterpret_cast<float4*>(&Bs[brow][bcol]) = bv;

        __syncthreads();

#pragma unroll
        for (int kk = 0; kk < 16; kk++) {
            float4 a = *reinterpret_cast<const float4*>(&As[kk][ty * 4]);
            float4 b = *reinterpret_cast<const float4*>(&Bs[kk][tx * 4]);
            float ar[4] = {a.x, a.y, a.z, a.w};
            float br[4] = {b.x, b.y, b.z, b.w};
#pragma unroll
            for (int i = 0; i < 4; i++)
#pragma unroll
                for (int j = 0; j < 4; j++)
                    acc[i][j] = fmaf(ar[i], br[j], acc[i][j]);
        }
        __syncthreads();
    }

#pragma unroll
    for (int i = 0; i < 4; i++) {
        const int gm = m0 + ty * 4 + i;
        if (gm < M) {
            float4 v = make_float4(acc[i][0], acc[i][1], acc[i][2], acc[i][3]);
            *reinterpret_cast<float4*>(C + (size_t)gm * N + n0 + tx * 4) = v;
        }
    }
}

// ---------------- CSR SpMM: warp per destination row, fused bias(+relu) -----
// out[r] = act( sum_{e in in(r)} w_e * sup[src_e] + bias )
// NF4 = F/4 float4 columns (64 or 32). Warp covers 32 float4 per chunk.
template<int NF4, bool RELU>
__global__ __launch_bounds__(256) void spmm_csr_kernel(
    const float4* __restrict__ sup,
    const int* __restrict__ row_ptr,
    const int* __restrict__ csr_src,
    const float* __restrict__ csr_w,
    const float4* __restrict__ bias,
    float4* __restrict__ out, int n)
{
    const int gtid = blockIdx.x * blockDim.x + threadIdx.x;
    const int r    = gtid >> 5;
    const int lane = gtid & 31;
    if (r >= n) return;

    const int start = row_ptr[r];
    const int end   = row_ptr[r + 1];

    float4 acc0 = make_float4(0.f, 0.f, 0.f, 0.f);
    float4 acc1 = make_float4(0.f, 0.f, 0.f, 0.f);

    for (int base = start; base < end; base += 32) {
        const int cnt = min(32, end - base);
        int   s_l = 0;
        float w_l = 0.f;
        if (lane < cnt) {
            s_l = csr_src[base + lane];
            w_l = csr_w[base + lane];
        }
#pragma unroll 4
        for (int k = 0; k < cnt; k++) {
            const int   s = __shfl_sync(0xffffffffu, s_l, k);
            const float w = __shfl_sync(0xffffffffu, w_l, k);
            const float4* __restrict__ row = sup + (size_t)s * NF4;
            float4 v0 = __ldg(row + lane);
            acc0.x = fmaf(w, v0.x, acc0.x);
            acc0.y = fmaf(w, v0.y, acc0.y);
            acc0.z = fmaf(w, v0.z, acc0.z);
            acc0.w = fmaf(w, v0.w, acc0.w);
            if (NF4 == 64) {
                float4 v1 = __ldg(row + 32 + lane);
                acc1.x = fmaf(w, v1.x, acc1.x);
                acc1.y = fmaf(w, v1.y, acc1.y);
                acc1.z = fmaf(w, v1.z, acc1.z);
                acc1.w = fmaf(w, v1.w, acc1.w);
            }
        }
    }

    // epilogue: bias (+ relu), single write
    float4 b0 = bias[lane];
    acc0.x += b0.x; acc0.y += b0.y; acc0.z += b0.z; acc0.w += b0.w;
    if (RELU) {
        acc0.x = fmaxf(acc0.x, 0.f); acc0.y = fmaxf(acc0.y, 0.f);
        acc0.z = fmaxf(acc0.z, 0.f); acc0.w = fmaxf(acc0.w, 0.f);
    }
    out[(size_t)r * NF4 + lane] = acc0;

    if (NF4 == 64) {
        float4 b1 = bias[32 + lane];
        acc1.x += b1.x; acc1.y += b1.y; acc1.z += b1.z; acc1.w += b1.w;
        if (RELU) {
            acc1.x = fmaxf(acc1.x, 0.f); acc1.y = fmaxf(acc1.y, 0.f);
            acc1.z = fmaxf(acc1.z, 0.f); acc1.w = fmaxf(acc1.w, 0.f);
        }
        out[(size_t)r * NF4 + 32 + lane] = acc1;
    }
}

// ---------------- head: concat(640) @ linW[640,16] + linb, log_softmax ------
__global__ __launch_bounds__(256) void head_kernel(
    const float* __restrict__ x1, const float* __restrict__ x2,
    const float* __restrict__ x3,
    const float* __restrict__ linW, const float* __restrict__ linb,
    float* __restrict__ out, int n)
{
    __shared__ float sW[640 * 16];
    for (int i = threadIdx.x; i < 640 * 16; i += blockDim.x) sW[i] = linW[i];
    __syncthreads();

    const int gtid = blockIdx.x * blockDim.x + threadIdx.x;
    const int node = gtid >> 4;
    const int c    = gtid & 15;
    if (node >= n) return;

    const float* __restrict__ r1 = x1 + (size_t)node * 256;
    const float* __restrict__ r2 = x2 + (size_t)node * 256;
    const float* __restrict__ r3 = x3 + (size_t)node * 128;

    float acc = linb[c];
#pragma unroll 4
    for (int k = 0; k < 256; k++) acc = fmaf(r1[k], sW[k * 16 + c], acc);
#pragma unroll 4
    for (int k = 0; k < 256; k++) acc = fmaf(r2[k], sW[(256 + k) * 16 + c], acc);
#pragma unroll 4
    for (int k = 0; k < 128; k++) acc = fmaf(r3[k], sW[(512 + k) * 16 + c], acc);

    float m = acc;
#pragma unroll
    for (int o = 8; o > 0; o >>= 1)
        m = fmaxf(m, __shfl_xor_sync(0xffffffffu, m, o));
    float ex = expf(acc - m);
    float ssum = ex;
#pragma unroll
    for (int o = 8; o > 0; o >>= 1)
        ssum += __shfl_xor_sync(0xffffffffu, ssum, o);

    out[(size_t)node * 16 + c] = acc - m - logf(ssum);
}

// ---------------- launch ----------------------------------------------------
extern "C" void kernel_launch(void* const* d_in, const int* in_sizes, int n_in,
                              void* d_out, int out_size)
{
    const float* x       = (const float*)d_in[0];
    const float* edge_w  = (const float*)d_in[1];
    const float* W1      = (const float*)d_in[2];
    const float* b1      = (const float*)d_in[3];
    const float* W2      = (const float*)d_in[4];
    const float* b2      = (const float*)d_in[5];
    const float* W3      = (const float*)d_in[6];
    const float* b3      = (const float*)d_in[7];
    const float* linW    = (const float*)d_in[8];
    const float* linb    = (const float*)d_in[9];
    const int*   esrc    = (const int*)d_in[10];
    const int*   edst    = (const int*)d_in[11];
    float*       out     = (float*)d_out;

    static float *sup = nullptr, *x1 = nullptr, *x2 = nullptr, *x3 = nullptr;
    static int *deg = nullptr, *cur = nullptr, *rp = nullptr, *csrc = nullptr;
    static float *cw = nullptr;
    if (!sup) {
        cudaGetSymbolAddress((void**)&sup,  g_support);
        cudaGetSymbolAddress((void**)&x1,   g_x1);
        cudaGetSymbolAddress((void**)&x2,   g_x2);
        cudaGetSymbolAddress((void**)&x3,   g_x3);
        cudaGetSymbolAddress((void**)&deg,  g_deg);
        cudaGetSymbolAddress((void**)&cur,  g_cursor);
        cudaGetSymbolAddress((void**)&rp,   g_row_ptr);
        cudaGetSymbolAddress((void**)&csrc, g_csr_src);
        cudaGetSymbolAddress((void**)&cw,   g_csr_w);
    }

    const int M = NN, E = EE;
    const int spmm_blocks = (M * 32 + 255) / 256;

    // ---- build dst-CSR once; reused by all 3 layers ----
    zero_int2_kernel<<<(M + 255) / 256, 256>>>(deg, cur, M);
    degree_kernel<<<(E + 255) / 256, 256>>>(edst, deg, E);
    scan_kernel<<<1, 1024>>>(deg, rp, M);
    scatter_kernel<<<(E + 255) / 256, 256>>>(esrc, edst, edge_w, rp, cur, csrc, cw, E);

    // ---- layer 1: support = x @ W1 ; x1 = relu(csr_spmm + b1) ----
    {
        dim3 grid((M + 63) / 64, 256 / 64);
        sgemm_kernel<<<grid, 256>>>(x, W1, sup, M, 512, 256);
        spmm_csr_kernel<64, true><<<spmm_blocks, 256>>>(
            (const float4*)sup, rp, csrc, cw, (const float4*)b1, (float4*)x1, M);
    }
    // ---- layer 2 ----
    {
        dim3 grid((M + 63) / 64, 256 / 64);
        sgemm_kernel<<<grid, 256>>>(x1, W2, sup, M, 256, 256);
        spmm_csr_kernel<64, true><<<spmm_blocks, 256>>>(
            (const float4*)sup, rp, csrc, cw, (const float4*)b2, (float4*)x2, M);
    }
    // ---- layer 3 (no relu) ----
    {
        dim3 grid((M + 63) / 64, 128 / 64);
        sgemm_kernel<<<grid, 256>>>(x2, W3, sup, M, 256, 128);
        spmm_csr_kernel<32, false><<<spmm_blocks, 256>>>(
            (const float4*)sup, rp, csrc, cw, (const float4*)b3, (float4*)x3, M);
    }
    // ---- head ----
    head_kernel<<<(M * 16 + 255) / 256, 256>>>(x1, x2, x3, linW, linb, out, M);
}

// round 6
// speedup vs baseline: 2.0082x; 1.2460x over previous
#include <cuda_runtime.h>
#include <cuda_bf16.h>
#include <cstddef>
#include <cstdint>

#define NN 50000
#define EE 1600000

// ---------------- scratch (static device globals; no allocation allowed) ----
__device__ __align__(16) float g_support[(size_t)NN * 256];
__device__ __align__(16) float g_x1[(size_t)NN * 256];
__device__ __align__(16) float g_x2[(size_t)NN * 256];
__device__ __align__(16) float g_x3[(size_t)NN * 128];

// CSR-by-destination scratch
__device__ int   g_deg[NN];
__device__ int   g_cursor[NN];
__device__ int   g_row_ptr[NN + 1];
__device__ int   g_csr_src[EE];
__device__ float g_csr_w[EE];

// ---------------- CSR build -------------------------------------------------
__global__ void zero_int2_kernel(int* __restrict__ a, int* __restrict__ b, int n) {
    int i = blockIdx.x * blockDim.x + threadIdx.x;
    if (i < n) { a[i] = 0; b[i] = 0; }
}

__global__ void degree_kernel(const int* __restrict__ dst, int* __restrict__ deg, int E) {
    int e = blockIdx.x * blockDim.x + threadIdx.x;
    if (e < E) atomicAdd(&deg[dst[e]], 1);
}

__global__ __launch_bounds__(1024) void scan_kernel(
    const int* __restrict__ deg, int* __restrict__ row_ptr, int n)
{
    __shared__ int ssum[1024];
    const int t  = threadIdx.x;
    const int CH = (n + 1023) / 1024;
    const int base = t * CH;

    int local = 0;
    for (int i = 0; i < CH; i++) {
        int idx = base + i;
        if (idx < n) local += deg[idx];
    }
    ssum[t] = local;
    __syncthreads();

    for (int off = 1; off < 1024; off <<= 1) {
        int add = (t >= off) ? ssum[t - off] : 0;
        __syncthreads();
        ssum[t] += add;
        __syncthreads();
    }

    int run = (t == 0) ? 0 : ssum[t - 1];
    for (int i = 0; i < CH; i++) {
        int idx = base + i;
        if (idx < n) { row_ptr[idx] = run; run += deg[idx]; }
    }
    if (t == 0) row_ptr[n] = ssum[1023];
}

__global__ void scatter_kernel(
    const int* __restrict__ src, const int* __restrict__ dst,
    const float* __restrict__ w,
    const int* __restrict__ row_ptr, int* __restrict__ cursor,
    int* __restrict__ csr_src, float* __restrict__ csr_w, int E)
{
    int e = blockIdx.x * blockDim.x + threadIdx.x;
    if (e >= E) return;
    int d   = dst[e];
    int pos = atomicAdd(&cursor[d], 1);
    int idx = row_ptr[d] + pos;
    csr_src[idx] = src[e];
    csr_w[idx]   = w[e];
}

// ---------------- tf32 tensor-core GEMM (3xTF32 split, fp32-accurate) -------
// C[M,N] = A[M,K] @ B[K,N], row-major. Block tile 128x64, BK=16.
// 8 warps, each owns a 32x32 warp tile = 2(m) x 4(n) m16n8k8 mma tiles.
// 3 mma passes per product: ah*bh + ah*bl + al*bh  (error ~2^-21).
__device__ __forceinline__ uint32_t f2tf32(float x) {
    uint32_t r;
    asm("cvt.rna.tf32.f32 %0, %1;" : "=r"(r) : "f"(x));
    return r;
}
__device__ __forceinline__ void split_tf32(float x, uint32_t& hi, uint32_t& lo) {
    hi = f2tf32(x);
    lo = f2tf32(x - __uint_as_float(hi));
}
__device__ __forceinline__ void mma_tf32(float c[4], const uint32_t a[4], const uint32_t b[2]) {
    asm volatile(
        "mma.sync.aligned.m16n8k8.row.col.f32.tf32.tf32.f32 "
        "{%0,%1,%2,%3}, {%4,%5,%6,%7}, {%8,%9}, {%0,%1,%2,%3};"
        : "+f"(c[0]), "+f"(c[1]), "+f"(c[2]), "+f"(c[3])
        : "r"(a[0]), "r"(a[1]), "r"(a[2]), "r"(a[3]), "r"(b[0]), "r"(b[1]));
}

__global__ __launch_bounds__(256) void tf32_gemm_kernel(
    const float* __restrict__ A, const float* __restrict__ B,
    float* __restrict__ C, int M, int K, int N)
{
    __shared__ float As[128][20];  // stride 20: conflict-free frag reads
    __shared__ float Bs[16][72];   // stride 72: conflict-free frag reads

    const int t    = threadIdx.x;
    const int wid  = t >> 5;
    const int lane = t & 31;
    const int wm   = (wid & 3) * 32;   // warp m offset in tile
    const int wn   = (wid >> 2) * 32;  // warp n offset in tile
    const int g    = lane >> 2;        // fragment group 0..7
    const int tg   = lane & 3;         // fragment thread-in-group 0..3

    const int m0 = blockIdx.x * 128;
    const int n0 = blockIdx.y * 64;

    // gmem tile-load mapping
    const int ar = t >> 2;            // A rows t>>2 and t>>2+64
    const int ac = (t & 3) * 4;       // A col4
    const int br = t >> 4;            // B row 0..15
    const int bc = (t & 15) * 4;      // B col4

    float c[2][4][4] = {};            // [mtile][ntile][frag]

    float4 aP0, aP1, bP;
    {
        const int gm0 = m0 + ar, gm1 = m0 + ar + 64;
        aP0 = (gm0 < M) ? *(const float4*)(A + (size_t)gm0 * K + ac) : make_float4(0,0,0,0);
        aP1 = (gm1 < M) ? *(const float4*)(A + (size_t)gm1 * K + ac) : make_float4(0,0,0,0);
        bP  = *(const float4*)(B + (size_t)br * N + n0 + bc);
    }

    for (int k0 = 0; k0 < K; k0 += 16) {
        // commit prefetched tile to smem
        *(float4*)&As[ar][ac]      = aP0;
        *(float4*)&As[ar + 64][ac] = aP1;
        *(float4*)&Bs[br][bc]      = bP;
        __syncthreads();

        // prefetch next tile
        if (k0 + 16 < K) {
            const int gm0 = m0 + ar, gm1 = m0 + ar + 64;
            const int kn = k0 + 16;
            aP0 = (gm0 < M) ? *(const float4*)(A + (size_t)gm0 * K + kn + ac) : make_float4(0,0,0,0);
            aP1 = (gm1 < M) ? *(const float4*)(A + (size_t)gm1 * K + kn + ac) : make_float4(0,0,0,0);
            bP  = *(const float4*)(B + (size_t)(kn + br) * N + n0 + bc);
        }

#pragma unroll
        for (int kk = 0; kk < 16; kk += 8) {
            // A fragments (2 m-tiles), split hi/lo once per k-slice
            uint32_t ah[2][4], al[2][4];
#pragma unroll
            for (int mt = 0; mt < 2; mt++) {
                const int r0 = wm + mt * 16 + g;
                split_tf32(As[r0][kk + tg],         ah[mt][0], al[mt][0]);
                split_tf32(As[r0 + 8][kk + tg],     ah[mt][1], al[mt][1]);
                split_tf32(As[r0][kk + tg + 4],     ah[mt][2], al[mt][2]);
                split_tf32(As[r0 + 8][kk + tg + 4], ah[mt][3], al[mt][3]);
            }
            // B fragments (4 n-tiles), split hi/lo once per k-slice
            uint32_t bh[4][2], bl[4][2];
#pragma unroll
            for (int nt = 0; nt < 4; nt++) {
                const int cn = wn + nt * 8 + g;
                split_tf32(Bs[kk + tg][cn],     bh[nt][0], bl[nt][0]);
                split_tf32(Bs[kk + tg + 4][cn], bh[nt][1], bl[nt][1]);
            }
            // 3xTF32 mma passes
#pragma unroll
            for (int mt = 0; mt < 2; mt++)
#pragma unroll
                for (int nt = 0; nt < 4; nt++) {
                    mma_tf32(c[mt][nt], ah[mt], bh[nt]);
                    mma_tf32(c[mt][nt], ah[mt], bl[nt]);
                    mma_tf32(c[mt][nt], al[mt], bh[nt]);
                }
        }
        __syncthreads();
    }

    // epilogue: c0,c1 -> (row g, cols tg*2, tg*2+1); c2,c3 -> row g+8
#pragma unroll
    for (int mt = 0; mt < 2; mt++)
#pragma unroll
        for (int nt = 0; nt < 4; nt++) {
            const int col = n0 + wn + nt * 8 + tg * 2;
            const int r0  = m0 + wm + mt * 16 + g;
            if (r0 < M)
                *(float2*)(C + (size_t)r0 * N + col) = make_float2(c[mt][nt][0], c[mt][nt][1]);
            if (r0 + 8 < M)
                *(float2*)(C + (size_t)(r0 + 8) * N + col) = make_float2(c[mt][nt][2], c[mt][nt][3]);
        }
}

// ---------------- CSR SpMM: warp per destination row, fused bias(+relu) -----
template<int NF4, bool RELU>
__global__ __launch_bounds__(256) void spmm_csr_kernel(
    const float4* __restrict__ sup,
    const int* __restrict__ row_ptr,
    const int* __restrict__ csr_src,
    const float* __restrict__ csr_w,
    const float4* __restrict__ bias,
    float4* __restrict__ out, int n)
{
    const int gtid = blockIdx.x * blockDim.x + threadIdx.x;
    const int r    = gtid >> 5;
    const int lane = gtid & 31;
    if (r >= n) return;

    const int start = row_ptr[r];
    const int end   = row_ptr[r + 1];

    float4 acc0 = make_float4(0.f, 0.f, 0.f, 0.f);
    float4 acc1 = make_float4(0.f, 0.f, 0.f, 0.f);

    for (int base = start; base < end; base += 32) {
        const int cnt = min(32, end - base);
        int   s_l = 0;
        float w_l = 0.f;
        if (lane < cnt) {
            s_l = csr_src[base + lane];
            w_l = csr_w[base + lane];
        }
#pragma unroll 4
        for (int k = 0; k < cnt; k++) {
            const int   s = __shfl_sync(0xffffffffu, s_l, k);
            const float w = __shfl_sync(0xffffffffu, w_l, k);
            const float4* __restrict__ row = sup + (size_t)s * NF4;
            float4 v0 = __ldg(row + lane);
            acc0.x = fmaf(w, v0.x, acc0.x);
            acc0.y = fmaf(w, v0.y, acc0.y);
            acc0.z = fmaf(w, v0.z, acc0.z);
            acc0.w = fmaf(w, v0.w, acc0.w);
            if (NF4 == 64) {
                float4 v1 = __ldg(row + 32 + lane);
                acc1.x = fmaf(w, v1.x, acc1.x);
                acc1.y = fmaf(w, v1.y, acc1.y);
                acc1.z = fmaf(w, v1.z, acc1.z);
                acc1.w = fmaf(w, v1.w, acc1.w);
            }
        }
    }

    float4 b0 = bias[lane];
    acc0.x += b0.x; acc0.y += b0.y; acc0.z += b0.z; acc0.w += b0.w;
    if (RELU) {
        acc0.x = fmaxf(acc0.x, 0.f); acc0.y = fmaxf(acc0.y, 0.f);
        acc0.z = fmaxf(acc0.z, 0.f); acc0.w = fmaxf(acc0.w, 0.f);
    }
    out[(size_t)r * NF4 + lane] = acc0;

    if (NF4 == 64) {
        float4 b1 = bias[32 + lane];
        acc1.x += b1.x; acc1.y += b1.y; acc1.z += b1.z; acc1.w += b1.w;
        if (RELU) {
            acc1.x = fmaxf(acc1.x, 0.f); acc1.y = fmaxf(acc1.y, 0.f);
            acc1.z = fmaxf(acc1.z, 0.f); acc1.w = fmaxf(acc1.w, 0.f);
        }
        out[(size_t)r * NF4 + 32 + lane] = acc1;
    }
}

// ---------------- head: concat(640) @ linW[640,16] + linb, log_softmax ------
__global__ __launch_bounds__(256) void head_kernel(
    const float* __restrict__ x1, const float* __restrict__ x2,
    const float* __restrict__ x3,
    const float* __restrict__ linW, const float* __restrict__ linb,
    float* __restrict__ out, int n)
{
    __shared__ float sW[640 * 16];
    for (int i = threadIdx.x; i < 640 * 16; i += blockDim.x) sW[i] = linW[i];
    __syncthreads();

    const int gtid = blockIdx.x * blockDim.x + threadIdx.x;
    const int node = gtid >> 4;
    const int c    = gtid & 15;
    if (node >= n) return;

    const float* __restrict__ r1 = x1 + (size_t)node * 256;
    const float* __restrict__ r2 = x2 + (size_t)node * 256;
    const float* __restrict__ r3 = x3 + (size_t)node * 128;

    float acc = linb[c];
#pragma unroll 4
    for (int k = 0; k < 256; k++) acc = fmaf(r1[k], sW[k * 16 + c], acc);
#pragma unroll 4
    for (int k = 0; k < 256; k++) acc = fmaf(r2[k], sW[(256 + k) * 16 + c], acc);
#pragma unroll 4
    for (int k = 0; k < 128; k++) acc = fmaf(r3[k], sW[(512 + k) * 16 + c], acc);

    float m = acc;
#pragma unroll
    for (int o = 8; o > 0; o >>= 1)
        m = fmaxf(m, __shfl_xor_sync(0xffffffffu, m, o));
    float ex = expf(acc - m);
    float ssum = ex;
#pragma unroll
    for (int o = 8; o > 0; o >>= 1)
        ssum += __shfl_xor_sync(0xffffffffu, ssum, o);

    out[(size_t)node * 16 + c] = acc - m - logf(ssum);
}

// ---------------- launch ----------------------------------------------------
extern "C" void kernel_launch(void* const* d_in, const int* in_sizes, int n_in,
                              void* d_out, int out_size)
{
    const float* x       = (const float*)d_in[0];
    const float* edge_w  = (const float*)d_in[1];
    const float* W1      = (const float*)d_in[2];
    const float* b1      = (const float*)d_in[3];
    const float* W2      = (const float*)d_in[4];
    const float* b2      = (const float*)d_in[5];
    const float* W3      = (const float*)d_in[6];
    const float* b3      = (const float*)d_in[7];
    const float* linW    = (const float*)d_in[8];
    const float* linb    = (const float*)d_in[9];
    const int*   esrc    = (const int*)d_in[10];
    const int*   edst    = (const int*)d_in[11];
    float*       out     = (float*)d_out;

    static float *sup = nullptr, *x1 = nullptr, *x2 = nullptr, *x3 = nullptr;
    static int *deg = nullptr, *cur = nullptr, *rp = nullptr, *csrc = nullptr;
    static float *cw = nullptr;
    if (!sup) {
        cudaGetSymbolAddress((void**)&sup,  g_support);
        cudaGetSymbolAddress((void**)&x1,   g_x1);
        cudaGetSymbolAddress((void**)&x2,   g_x2);
        cudaGetSymbolAddress((void**)&x3,   g_x3);
        cudaGetSymbolAddress((void**)&deg,  g_deg);
        cudaGetSymbolAddress((void**)&cur,  g_cursor);
        cudaGetSymbolAddress((void**)&rp,   g_row_ptr);
        cudaGetSymbolAddress((void**)&csrc, g_csr_src);
        cudaGetSymbolAddress((void**)&cw,   g_csr_w);
    }

    const int M = NN, E = EE;
    const int spmm_blocks = (M * 32 + 255) / 256;

    // ---- build dst-CSR once; reused by all 3 layers ----
    zero_int2_kernel<<<(M + 255) / 256, 256>>>(deg, cur, M);
    degree_kernel<<<(E + 255) / 256, 256>>>(edst, deg, E);
    scan_kernel<<<1, 1024>>>(deg, rp, M);
    scatter_kernel<<<(E + 255) / 256, 256>>>(esrc, edst, edge_w, rp, cur, csrc, cw, E);

    // ---- layer 1: support = x @ W1 ; x1 = relu(csr_spmm + b1) ----
    {
        dim3 grid((M + 127) / 128, 256 / 64);
        tf32_gemm_kernel<<<grid, 256>>>(x, W1, sup, M, 512, 256);
        spmm_csr_kernel<64, true><<<spmm_blocks, 256>>>(
            (const float4*)sup, rp, csrc, cw, (const float4*)b1, (float4*)x1, M);
    }
    // ---- layer 2 ----
    {
        dim3 grid((M + 127) / 128, 256 / 64);
        tf32_gemm_kernel<<<grid, 256>>>(x1, W2, sup, M, 256, 256);
        spmm_csr_kernel<64, true><<<spmm_blocks, 256>>>(
            (const float4*)sup, rp, csrc, cw, (const float4*)b2, (float4*)x2, M);
    }
    // ---- layer 3 (no relu) ----
    {
        dim3 grid((M + 127) / 128, 128 / 64);
        tf32_gemm_kernel<<<grid, 256>>>(x2, W3, sup, M, 256, 128);
        spmm_csr_kernel<32, false><<<spmm_blocks, 256>>>(
            (const float4*)sup, rp, csrc, cw, (const float4*)b3, (float4*)x3, M);
    }
    // ---- head ----
    head_kernel<<<(M * 16 + 255) / 256, 256>>>(x1, x2, x3, linW, linb, out, M);
}

// round 7
// speedup vs baseline: 2.0886x; 1.0401x over previous
#include <cuda_runtime.h>
#include <cuda_bf16.h>
#include <cstddef>
#include <cstdint>

#define NN 50000
#define EE 1600000

// ---------------- scratch (static device globals; no allocation allowed) ----
__device__ __align__(16) __nv_bfloat16 g_supb[(size_t)NN * 256];  // support, bf16
__device__ __align__(16) float g_x1[(size_t)NN * 256];
__device__ __align__(16) float g_x2[(size_t)NN * 256];
__device__ __align__(16) float g_x3[(size_t)NN * 128];

// CSR-by-destination scratch
__device__ int   g_deg[NN];
__device__ int   g_cursor[NN];
__device__ int   g_row_ptr[NN + 1];
__device__ int   g_csr_src[EE];
__device__ float g_csr_w[EE];

// ---------------- CSR build -------------------------------------------------
__global__ void zero_int2_kernel(int* __restrict__ a, int* __restrict__ b, int n) {
    int i = blockIdx.x * blockDim.x + threadIdx.x;
    if (i < n) { a[i] = 0; b[i] = 0; }
}

__global__ void degree_kernel(const int* __restrict__ dst, int* __restrict__ deg, int E) {
    int e = blockIdx.x * blockDim.x + threadIdx.x;
    if (e < E) atomicAdd(&deg[dst[e]], 1);
}

__global__ __launch_bounds__(1024) void scan_kernel(
    const int* __restrict__ deg, int* __restrict__ row_ptr, int n)
{
    __shared__ int ssum[1024];
    const int t  = threadIdx.x;
    const int CH = (n + 1023) / 1024;
    const int base = t * CH;

    int local = 0;
    for (int i = 0; i < CH; i++) {
        int idx = base + i;
        if (idx < n) local += deg[idx];
    }
    ssum[t] = local;
    __syncthreads();

    for (int off = 1; off < 1024; off <<= 1) {
        int add = (t >= off) ? ssum[t - off] : 0;
        __syncthreads();
        ssum[t] += add;
        __syncthreads();
    }

    int run = (t == 0) ? 0 : ssum[t - 1];
    for (int i = 0; i < CH; i++) {
        int idx = base + i;
        if (idx < n) { row_ptr[idx] = run; run += deg[idx]; }
    }
    if (t == 0) row_ptr[n] = ssum[1023];
}

__global__ void scatter_kernel(
    const int* __restrict__ src, const int* __restrict__ dst,
    const float* __restrict__ w,
    const int* __restrict__ row_ptr, int* __restrict__ cursor,
    int* __restrict__ csr_src, float* __restrict__ csr_w, int E)
{
    int e = blockIdx.x * blockDim.x + threadIdx.x;
    if (e >= E) return;
    int d   = dst[e];
    int pos = atomicAdd(&cursor[d], 1);
    int idx = row_ptr[d] + pos;
    csr_src[idx] = src[e];
    csr_w[idx]   = w[e];
}

// ---------------- tf32 tensor-core GEMM (3xTF32 split), bf16 output ---------
// C[M,N] = A[M,K] @ B[K,N], row-major fp32 in, bf16 out (support only).
__device__ __forceinline__ uint32_t f2tf32(float x) {
    uint32_t r;
    asm("cvt.rna.tf32.f32 %0, %1;" : "=r"(r) : "f"(x));
    return r;
}
__device__ __forceinline__ void split_tf32(float x, uint32_t& hi, uint32_t& lo) {
    hi = f2tf32(x);
    lo = f2tf32(x - __uint_as_float(hi));
}
__device__ __forceinline__ void mma_tf32(float c[4], const uint32_t a[4], const uint32_t b[2]) {
    asm volatile(
        "mma.sync.aligned.m16n8k8.row.col.f32.tf32.tf32.f32 "
        "{%0,%1,%2,%3}, {%4,%5,%6,%7}, {%8,%9}, {%0,%1,%2,%3};"
        : "+f"(c[0]), "+f"(c[1]), "+f"(c[2]), "+f"(c[3])
        : "r"(a[0]), "r"(a[1]), "r"(a[2]), "r"(a[3]), "r"(b[0]), "r"(b[1]));
}

__global__ __launch_bounds__(256) void tf32_gemm_kernel(
    const float* __restrict__ A, const float* __restrict__ B,
    __nv_bfloat16* __restrict__ C, int M, int K, int N)
{
    __shared__ float As[128][20];
    __shared__ float Bs[16][72];

    const int t    = threadIdx.x;
    const int wid  = t >> 5;
    const int lane = t & 31;
    const int wm   = (wid & 3) * 32;
    const int wn   = (wid >> 2) * 32;
    const int g    = lane >> 2;
    const int tg   = lane & 3;

    const int m0 = blockIdx.x * 128;
    const int n0 = blockIdx.y * 64;

    const int ar = t >> 2;
    const int ac = (t & 3) * 4;
    const int br = t >> 4;
    const int bc = (t & 15) * 4;

    float c[2][4][4] = {};

    float4 aP0, aP1, bP;
    {
        const int gm0 = m0 + ar, gm1 = m0 + ar + 64;
        aP0 = (gm0 < M) ? *(const float4*)(A + (size_t)gm0 * K + ac) : make_float4(0,0,0,0);
        aP1 = (gm1 < M) ? *(const float4*)(A + (size_t)gm1 * K + ac) : make_float4(0,0,0,0);
        bP  = *(const float4*)(B + (size_t)br * N + n0 + bc);
    }

    for (int k0 = 0; k0 < K; k0 += 16) {
        *(float4*)&As[ar][ac]      = aP0;
        *(float4*)&As[ar + 64][ac] = aP1;
        *(float4*)&Bs[br][bc]      = bP;
        __syncthreads();

        if (k0 + 16 < K) {
            const int gm0 = m0 + ar, gm1 = m0 + ar + 64;
            const int kn = k0 + 16;
            aP0 = (gm0 < M) ? *(const float4*)(A + (size_t)gm0 * K + kn + ac) : make_float4(0,0,0,0);
            aP1 = (gm1 < M) ? *(const float4*)(A + (size_t)gm1 * K + kn + ac) : make_float4(0,0,0,0);
            bP  = *(const float4*)(B + (size_t)(kn + br) * N + n0 + bc);
        }

#pragma unroll
        for (int kk = 0; kk < 16; kk += 8) {
            uint32_t ah[2][4], al[2][4];
#pragma unroll
            for (int mt = 0; mt < 2; mt++) {
                const int r0 = wm + mt * 16 + g;
                split_tf32(As[r0][kk + tg],         ah[mt][0], al[mt][0]);
                split_tf32(As[r0 + 8][kk + tg],     ah[mt][1], al[mt][1]);
                split_tf32(As[r0][kk + tg + 4],     ah[mt][2], al[mt][2]);
                split_tf32(As[r0 + 8][kk + tg + 4], ah[mt][3], al[mt][3]);
            }
            uint32_t bh[4][2], bl[4][2];
#pragma unroll
            for (int nt = 0; nt < 4; nt++) {
                const int cn = wn + nt * 8 + g;
                split_tf32(Bs[kk + tg][cn],     bh[nt][0], bl[nt][0]);
                split_tf32(Bs[kk + tg + 4][cn], bh[nt][1], bl[nt][1]);
            }
#pragma unroll
            for (int mt = 0; mt < 2; mt++)
#pragma unroll
                for (int nt = 0; nt < 4; nt++) {
                    mma_tf32(c[mt][nt], ah[mt], bh[nt]);
                    mma_tf32(c[mt][nt], ah[mt], bl[nt]);
                    mma_tf32(c[mt][nt], al[mt], bh[nt]);
                }
        }
        __syncthreads();
    }

    // epilogue: round-to-nearest bf16, paired stores (col always even)
#pragma unroll
    for (int mt = 0; mt < 2; mt++)
#pragma unroll
        for (int nt = 0; nt < 4; nt++) {
            const int col = n0 + wn + nt * 8 + tg * 2;
            const int r0  = m0 + wm + mt * 16 + g;
            if (r0 < M)
                *(__nv_bfloat162*)(C + (size_t)r0 * N + col) =
                    __floats2bfloat162_rn(c[mt][nt][0], c[mt][nt][1]);
            if (r0 + 8 < M)
                *(__nv_bfloat162*)(C + (size_t)(r0 + 8) * N + col) =
                    __floats2bfloat162_rn(c[mt][nt][2], c[mt][nt][3]);
        }
}

// ---------------- CSR SpMM over bf16 support, fp32 accumulate ---------------
// F=256: lane owns cols [lane*8, lane*8+8), one uint4 (8 bf16) per edge.
// F=128: lane owns cols [lane*4, lane*4+4), one uint2 (4 bf16) per edge.
template<int F, bool RELU>
__global__ __launch_bounds__(256) void spmm_bf16_kernel(
    const __nv_bfloat16* __restrict__ sup,
    const int* __restrict__ row_ptr,
    const int* __restrict__ csr_src,
    const float* __restrict__ csr_w,
    const float* __restrict__ bias,
    float* __restrict__ out, int n)
{
    constexpr int PL = F / 32;          // floats per lane (8 or 4)
    const int gtid = blockIdx.x * blockDim.x + threadIdx.x;
    const int r    = gtid >> 5;
    const int lane = gtid & 31;
    if (r >= n) return;

    const int start = row_ptr[r];
    const int end   = row_ptr[r + 1];

    float acc[PL];
#pragma unroll
    for (int j = 0; j < PL; j++) acc[j] = 0.f;

    for (int base = start; base < end; base += 32) {
        const int cnt = min(32, end - base);
        int   s_l = 0;
        float w_l = 0.f;
        if (lane < cnt) {
            s_l = csr_src[base + lane];
            w_l = csr_w[base + lane];
        }
#pragma unroll 4
        for (int k = 0; k < cnt; k++) {
            const int   s = __shfl_sync(0xffffffffu, s_l, k);
            const float w = __shfl_sync(0xffffffffu, w_l, k);
            const __nv_bfloat16* __restrict__ row = sup + (size_t)s * F;
            if (F == 256) {
                const uint4 v = __ldg((const uint4*)row + lane);
                float2 f0 = __bfloat1622float2(*(const __nv_bfloat162*)&v.x);
                float2 f1 = __bfloat1622float2(*(const __nv_bfloat162*)&v.y);
                float2 f2 = __bfloat1622float2(*(const __nv_bfloat162*)&v.z);
                float2 f3 = __bfloat1622float2(*(const __nv_bfloat162*)&v.w);
                acc[0] = fmaf(w, f0.x, acc[0]); acc[1] = fmaf(w, f0.y, acc[1]);
                acc[2] = fmaf(w, f1.x, acc[2]); acc[3] = fmaf(w, f1.y, acc[3]);
                acc[4] = fmaf(w, f2.x, acc[4]); acc[5] = fmaf(w, f2.y, acc[5]);
                acc[6] = fmaf(w, f3.x, acc[6]); acc[7] = fmaf(w, f3.y, acc[7]);
            } else {
                const uint2 v = __ldg((const uint2*)row + lane);
                float2 f0 = __bfloat1622float2(*(const __nv_bfloat162*)&v.x);
                float2 f1 = __bfloat1622float2(*(const __nv_bfloat162*)&v.y);
                acc[0] = fmaf(w, f0.x, acc[0]); acc[1] = fmaf(w, f0.y, acc[1]);
                acc[2] = fmaf(w, f1.x, acc[2]); acc[3] = fmaf(w, f1.y, acc[3]);
            }
        }
    }

    // epilogue: bias (+ relu), coalesced float4 stores
    const int c0 = lane * PL;
#pragma unroll
    for (int j = 0; j < PL; j++) {
        acc[j] += bias[c0 + j];
        if (RELU) acc[j] = fmaxf(acc[j], 0.f);
    }
    float* __restrict__ orow = out + (size_t)r * F + c0;
#pragma unroll
    for (int j = 0; j < PL; j += 4)
        *(float4*)(orow + j) = make_float4(acc[j], acc[j+1], acc[j+2], acc[j+3]);
}

// ---------------- head: concat(640) @ linW[640,16] + linb, log_softmax ------
__global__ __launch_bounds__(256) void head_kernel(
    const float* __restrict__ x1, const float* __restrict__ x2,
    const float* __restrict__ x3,
    const float* __restrict__ linW, const float* __restrict__ linb,
    float* __restrict__ out, int n)
{
    __shared__ float sW[640 * 16];
    for (int i = threadIdx.x; i < 640 * 16; i += blockDim.x) sW[i] = linW[i];
    __syncthreads();

    const int gtid = blockIdx.x * blockDim.x + threadIdx.x;
    const int node = gtid >> 4;
    const int c    = gtid & 15;
    if (node >= n) return;

    const float* __restrict__ r1 = x1 + (size_t)node * 256;
    const float* __restrict__ r2 = x2 + (size_t)node * 256;
    const float* __restrict__ r3 = x3 + (size_t)node * 128;

    float acc = linb[c];
#pragma unroll 4
    for (int k = 0; k < 256; k++) acc = fmaf(r1[k], sW[k * 16 + c], acc);
#pragma unroll 4
    for (int k = 0; k < 256; k++) acc = fmaf(r2[k], sW[(256 + k) * 16 + c], acc);
#pragma unroll 4
    for (int k = 0; k < 128; k++) acc = fmaf(r3[k], sW[(512 + k) * 16 + c], acc);

    float m = acc;
#pragma unroll
    for (int o = 8; o > 0; o >>= 1)
        m = fmaxf(m, __shfl_xor_sync(0xffffffffu, m, o));
    float ex = expf(acc - m);
    float ssum = ex;
#pragma unroll
    for (int o = 8; o > 0; o >>= 1)
        ssum += __shfl_xor_sync(0xffffffffu, ssum, o);

    out[(size_t)node * 16 + c] = acc - m - logf(ssum);
}

// ---------------- launch ----------------------------------------------------
extern "C" void kernel_launch(void* const* d_in, const int* in_sizes, int n_in,
                              void* d_out, int out_size)
{
    const float* x       = (const float*)d_in[0];
    const float* edge_w  = (const float*)d_in[1];
    const float* W1      = (const float*)d_in[2];
    const float* b1      = (const float*)d_in[3];
    const float* W2      = (const float*)d_in[4];
    const float* b2      = (const float*)d_in[5];
    const float* W3      = (const float*)d_in[6];
    const float* b3      = (const float*)d_in[7];
    const float* linW    = (const float*)d_in[8];
    const float* linb    = (const float*)d_in[9];
    const int*   esrc    = (const int*)d_in[10];
    const int*   edst    = (const int*)d_in[11];
    float*       out     = (float*)d_out;

    static __nv_bfloat16 *supb = nullptr;
    static float *x1 = nullptr, *x2 = nullptr, *x3 = nullptr;
    static int *deg = nullptr, *cur = nullptr, *rp = nullptr, *csrc = nullptr;
    static float *cw = nullptr;
    if (!supb) {
        cudaGetSymbolAddress((void**)&supb, g_supb);
        cudaGetSymbolAddress((void**)&x1,   g_x1);
        cudaGetSymbolAddress((void**)&x2,   g_x2);
        cudaGetSymbolAddress((void**)&x3,   g_x3);
        cudaGetSymbolAddress((void**)&deg,  g_deg);
        cudaGetSymbolAddress((void**)&cur,  g_cursor);
        cudaGetSymbolAddress((void**)&rp,   g_row_ptr);
        cudaGetSymbolAddress((void**)&csrc, g_csr_src);
        cudaGetSymbolAddress((void**)&cw,   g_csr_w);
    }

    const int M = NN, E = EE;
    const int spmm_blocks = (M * 32 + 255) / 256;

    // ---- build dst-CSR once; reused by all 3 layers ----
    zero_int2_kernel<<<(M + 255) / 256, 256>>>(deg, cur, M);
    degree_kernel<<<(E + 255) / 256, 256>>>(edst, deg, E);
    scan_kernel<<<1, 1024>>>(deg, rp, M);
    scatter_kernel<<<(E + 255) / 256, 256>>>(esrc, edst, edge_w, rp, cur, csrc, cw, E);

    // ---- layer 1: support = bf16(x @ W1) ; x1 = relu(csr_spmm + b1) ----
    {
        dim3 grid((M + 127) / 128, 256 / 64);
        tf32_gemm_kernel<<<grid, 256>>>(x, W1, supb, M, 512, 256);
        spmm_bf16_kernel<256, true><<<spmm_blocks, 256>>>(
            supb, rp, csrc, cw, b1, x1, M);
    }
    // ---- layer 2 ----
    {
        dim3 grid((M + 127) / 128, 256 / 64);
        tf32_gemm_kernel<<<grid, 256>>>(x1, W2, supb, M, 256, 256);
        spmm_bf16_kernel<256, true><<<spmm_blocks, 256>>>(
            supb, rp, csrc, cw, b2, x2, M);
    }
    // ---- layer 3 (no relu) ----
    {
        dim3 grid((M + 127) / 128, 128 / 64);
        tf32_gemm_kernel<<<grid, 256>>>(x2, W3, supb, M, 256, 128);
        spmm_bf16_kernel<128, false><<<spmm_blocks, 256>>>(
            supb, rp, csrc, cw, b3, x3, M);
    }
    // ---- head ----
    head_kernel<<<(M * 16 + 255) / 256, 256>>>(x1, x2, x3, linW, linb, out, M);
}

// round 9
// speedup vs baseline: 2.3410x; 1.1208x over previous
#include <cuda_runtime.h>
#include <cuda_bf16.h>
#include <cstddef>
#include <cstdint>

#define NN 50000
#define EE 1600000

// ---------------- scratch (static device globals; no allocation allowed) ----
__device__ __align__(16) __nv_bfloat16 g_supb[(size_t)NN * 256];  // support, bf16
__device__ __align__(16) float g_x1[(size_t)NN * 256];
__device__ __align__(16) float g_x2[(size_t)NN * 256];
__device__ __align__(16) float g_x3[(size_t)NN * 128];

// CSR-by-destination scratch
__device__ int   g_deg[NN];
__device__ int   g_cursor[NN];
__device__ int   g_row_ptr[NN + 1];
__device__ int   g_csr_src[EE];
__device__ float g_csr_w[EE];

// ---------------- CSR build -------------------------------------------------
__global__ void zero_int2_kernel(int* __restrict__ a, int* __restrict__ b, int n) {
    int i = blockIdx.x * blockDim.x + threadIdx.x;
    if (i < n) { a[i] = 0; b[i] = 0; }
}

__global__ void degree_kernel(const int* __restrict__ dst, int* __restrict__ deg, int E) {
    int e = blockIdx.x * blockDim.x + threadIdx.x;
    if (e < E) atomicAdd(&deg[dst[e]], 1);
}

__global__ __launch_bounds__(1024) void scan_kernel(
    const int* __restrict__ deg, int* __restrict__ row_ptr, int n)
{
    __shared__ int ssum[1024];
    const int t  = threadIdx.x;
    const int CH = (n + 1023) / 1024;
    const int base = t * CH;

    int local = 0;
    for (int i = 0; i < CH; i++) {
        int idx = base + i;
        if (idx < n) local += deg[idx];
    }
    ssum[t] = local;
    __syncthreads();

    for (int off = 1; off < 1024; off <<= 1) {
        int add = (t >= off) ? ssum[t - off] : 0;
        __syncthreads();
        ssum[t] += add;
        __syncthreads();
    }

    int run = (t == 0) ? 0 : ssum[t - 1];
    for (int i = 0; i < CH; i++) {
        int idx = base + i;
        if (idx < n) { row_ptr[idx] = run; run += deg[idx]; }
    }
    if (t == 0) row_ptr[n] = ssum[1023];
}

__global__ void scatter_kernel(
    const int* __restrict__ src, const int* __restrict__ dst,
    const float* __restrict__ w,
    const int* __restrict__ row_ptr, int* __restrict__ cursor,
    int* __restrict__ csr_src, float* __restrict__ csr_w, int E)
{
    int e = blockIdx.x * blockDim.x + threadIdx.x;
    if (e >= E) return;
    int d   = dst[e];
    int pos = atomicAdd(&cursor[d], 1);
    int idx = row_ptr[d] + pos;
    csr_src[idx] = src[e];
    csr_w[idx]   = w[e];
}

// ---------------- 3xBF16 tensor-core GEMM (m16n8k16), bf16 output -----------
// C[M,N] = A[M,K] @ B[K,N], row-major fp32 in, bf16 out.
// Each fp32 operand split hi+lo in bf16; 3 passes hh+hl+lh -> ~2^-17 error.
__device__ __forceinline__ void split_bf16x2(float x0, float x1,
                                             uint32_t& hi, uint32_t& lo) {
    __nv_bfloat162 h = __floats2bfloat162_rn(x0, x1);
    float r0 = x0 - __bfloat162float(h.x);
    float r1 = x1 - __bfloat162float(h.y);
    __nv_bfloat162 l = __floats2bfloat162_rn(r0, r1);
    hi = *reinterpret_cast<uint32_t*>(&h);
    lo = *reinterpret_cast<uint32_t*>(&l);
}
__device__ __forceinline__ void mma_bf16(float c[4], const uint32_t a[4], const uint32_t b[2]) {
    asm volatile(
        "mma.sync.aligned.m16n8k16.row.col.f32.bf16.bf16.f32 "
        "{%0,%1,%2,%3}, {%4,%5,%6,%7}, {%8,%9}, {%0,%1,%2,%3};"
        : "+f"(c[0]), "+f"(c[1]), "+f"(c[2]), "+f"(c[3])
        : "r"(a[0]), "r"(a[1]), "r"(a[2]), "r"(a[3]), "r"(b[0]), "r"(b[1]));
}

__global__ __launch_bounds__(256) void bf16_gemm_kernel(
    const float* __restrict__ A, const float* __restrict__ B,
    __nv_bfloat16* __restrict__ C, int M, int K, int N)
{
    __shared__ float As[128][20];
    __shared__ float Bs[16][72];

    const int t    = threadIdx.x;
    const int wid  = t >> 5;
    const int lane = t & 31;
    const int wm   = (wid & 3) * 32;
    const int wn   = (wid >> 2) * 32;
    const int g    = lane >> 2;
    const int tg2  = (lane & 3) * 2;   // k-pair base 0,2,4,6

    const int m0 = blockIdx.x * 128;
    const int n0 = blockIdx.y * 64;

    const int ar = t >> 2;
    const int ac = (t & 3) * 4;
    const int br = t >> 4;
    const int bc = (t & 15) * 4;

    float c[2][4][4] = {};

    float4 aP0, aP1, bP;
    {
        const int gm0 = m0 + ar, gm1 = m0 + ar + 64;
        aP0 = (gm0 < M) ? *(const float4*)(A + (size_t)gm0 * K + ac) : make_float4(0,0,0,0);
        aP1 = (gm1 < M) ? *(const float4*)(A + (size_t)gm1 * K + ac) : make_float4(0,0,0,0);
        bP  = *(const float4*)(B + (size_t)br * N + n0 + bc);
    }

    for (int k0 = 0; k0 < K; k0 += 16) {
        *(float4*)&As[ar][ac]      = aP0;
        *(float4*)&As[ar + 64][ac] = aP1;
        *(float4*)&Bs[br][bc]      = bP;
        __syncthreads();

        if (k0 + 16 < K) {
            const int gm0 = m0 + ar, gm1 = m0 + ar + 64;
            const int kn = k0 + 16;
            aP0 = (gm0 < M) ? *(const float4*)(A + (size_t)gm0 * K + kn + ac) : make_float4(0,0,0,0);
            aP1 = (gm1 < M) ? *(const float4*)(A + (size_t)gm1 * K + kn + ac) : make_float4(0,0,0,0);
            bP  = *(const float4*)(B + (size_t)(kn + br) * N + n0 + bc);
        }

        // one full k16 slice per tile
        uint32_t ah[2][4], al[2][4];
#pragma unroll
        for (int mt = 0; mt < 2; mt++) {
            const int r0 = wm + mt * 16 + g;
            split_bf16x2(As[r0][tg2],         As[r0][tg2 + 1],     ah[mt][0], al[mt][0]);
            split_bf16x2(As[r0 + 8][tg2],     As[r0 + 8][tg2 + 1], ah[mt][1], al[mt][1]);
            split_bf16x2(As[r0][tg2 + 8],     As[r0][tg2 + 9],     ah[mt][2], al[mt][2]);
            split_bf16x2(As[r0 + 8][tg2 + 8], As[r0 + 8][tg2 + 9], ah[mt][3], al[mt][3]);
        }
        uint32_t bh[4][2], bl[4][2];
#pragma unroll
        for (int nt = 0; nt < 4; nt++) {
            const int cn = wn + nt * 8 + g;
            split_bf16x2(Bs[tg2][cn],     Bs[tg2 + 1][cn], bh[nt][0], bl[nt][0]);
            split_bf16x2(Bs[tg2 + 8][cn], Bs[tg2 + 9][cn], bh[nt][1], bl[nt][1]);
        }
#pragma unroll
        for (int mt = 0; mt < 2; mt++)
#pragma unroll
            for (int nt = 0; nt < 4; nt++) {
                mma_bf16(c[mt][nt], ah[mt], bh[nt]);
                mma_bf16(c[mt][nt], ah[mt], bl[nt]);
                mma_bf16(c[mt][nt], al[mt], bh[nt]);
            }
        __syncthreads();
    }

    // epilogue: round-to-nearest bf16, paired stores (col always even)
#pragma unroll
    for (int mt = 0; mt < 2; mt++)
#pragma unroll
        for (int nt = 0; nt < 4; nt++) {
            const int col = n0 + wn + nt * 8 + tg2;
            const int r0  = m0 + wm + mt * 16 + g;
            if (r0 < M)
                *(__nv_bfloat162*)(C + (size_t)r0 * N + col) =
                    __floats2bfloat162_rn(c[mt][nt][0], c[mt][nt][1]);
            if (r0 + 8 < M)
                *(__nv_bfloat162*)(C + (size_t)(r0 + 8) * N + col) =
                    __floats2bfloat162_rn(c[mt][nt][2], c[mt][nt][3]);
        }
}

// ---------------- CSR SpMM over bf16 support, fp32 accumulate ---------------
template<int F, bool RELU>
__global__ __launch_bounds__(256) void spmm_bf16_kernel(
    const __nv_bfloat16* __restrict__ sup,
    const int* __restrict__ row_ptr,
    const int* __restrict__ csr_src,
    const float* __restrict__ csr_w,
    const float* __restrict__ bias,
    float* __restrict__ out, int n)
{
    constexpr int PL = F / 32;          // floats per lane (8 or 4)
    const int gtid = blockIdx.x * blockDim.x + threadIdx.x;
    const int r    = gtid >> 5;
    const int lane = gtid & 31;
    if (r >= n) return;

    const int start = row_ptr[r];
    const int end   = row_ptr[r + 1];

    float acc[PL];
#pragma unroll
    for (int j = 0; j < PL; j++) acc[j] = 0.f;

    for (int base = start; base < end; base += 32) {
        const int cnt = min(32, end - base);
        int   s_l = 0;
        float w_l = 0.f;
        if (lane < cnt) {
            s_l = csr_src[base + lane];
            w_l = csr_w[base + lane];
        }
#pragma unroll 4
        for (int k = 0; k < cnt; k++) {
            const int   s = __shfl_sync(0xffffffffu, s_l, k);
            const float w = __shfl_sync(0xffffffffu, w_l, k);
            const __nv_bfloat16* __restrict__ row = sup + (size_t)s * F;
            if (F == 256) {
                const uint4 v = __ldg((const uint4*)row + lane);
                float2 f0 = __bfloat1622float2(*(const __nv_bfloat162*)&v.x);
                float2 f1 = __bfloat1622float2(*(const __nv_bfloat162*)&v.y);
                float2 f2 = __bfloat1622float2(*(const __nv_bfloat162*)&v.z);
                float2 f3 = __bfloat1622float2(*(const __nv_bfloat162*)&v.w);
                acc[0] = fmaf(w, f0.x, acc[0]); acc[1] = fmaf(w, f0.y, acc[1]);
                acc[2] = fmaf(w, f1.x, acc[2]); acc[3] = fmaf(w, f1.y, acc[3]);
                acc[4] = fmaf(w, f2.x, acc[4]); acc[5] = fmaf(w, f2.y, acc[5]);
                acc[6] = fmaf(w, f3.x, acc[6]); acc[7] = fmaf(w, f3.y, acc[7]);
            } else {
                const uint2 v = __ldg((const uint2*)row + lane);
                float2 f0 = __bfloat1622float2(*(const __nv_bfloat162*)&v.x);
                float2 f1 = __bfloat1622float2(*(const __nv_bfloat162*)&v.y);
                acc[0] = fmaf(w, f0.x, acc[0]); acc[1] = fmaf(w, f0.y, acc[1]);
                acc[2] = fmaf(w, f1.x, acc[2]); acc[3] = fmaf(w, f1.y, acc[3]);
            }
        }
    }

    const int c0 = lane * PL;
#pragma unroll
    for (int j = 0; j < PL; j++) {
        acc[j] += bias[c0 + j];
        if (RELU) acc[j] = fmaxf(acc[j], 0.f);
    }
    float* __restrict__ orow = out + (size_t)r * F + c0;
#pragma unroll
    for (int j = 0; j < PL; j += 4)
        *(float4*)(orow + j) = make_float4(acc[j], acc[j+1], acc[j+2], acc[j+3]);
}

// ---------------- head: concat(640) @ linW[640,16] + linb, log_softmax ------
__global__ __launch_bounds__(256) void head_kernel(
    const float* __restrict__ x1, const float* __restrict__ x2,
    const float* __restrict__ x3,
    const float* __restrict__ linW, const float* __restrict__ linb,
    float* __restrict__ out, int n)
{
    __shared__ float sW[640 * 16];
    for (int i = threadIdx.x; i < 640 * 16; i += blockDim.x) sW[i] = linW[i];
    __syncthreads();

    const int gtid = blockIdx.x * blockDim.x + threadIdx.x;
    const int node = gtid >> 4;
    const int c    = gtid & 15;
    if (node >= n) return;

    const float* __restrict__ r1 = x1 + (size_t)node * 256;
    const float* __restrict__ r2 = x2 + (size_t)node * 256;
    const float* __restrict__ r3 = x3 + (size_t)node * 128;

    float acc = linb[c];
#pragma unroll 4
    for (int k = 0; k < 256; k++) acc = fmaf(r1[k], sW[k * 16 + c], acc);
#pragma unroll 4
    for (int k = 0; k < 256; k++) acc = fmaf(r2[k], sW[(256 + k) * 16 + c], acc);
#pragma unroll 4
    for (int k = 0; k < 128; k++) acc = fmaf(r3[k], sW[(512 + k) * 16 + c], acc);

    float m = acc;
#pragma unroll
    for (int o = 8; o > 0; o >>= 1)
        m = fmaxf(m, __shfl_xor_sync(0xffffffffu, m, o));
    float ex = expf(acc - m);
    float ssum = ex;
#pragma unroll
    for (int o = 8; o > 0; o >>= 1)
        ssum += __shfl_xor_sync(0xffffffffu, ssum, o);

    out[(size_t)node * 16 + c] = acc - m - logf(ssum);
}

// ---------------- launch ----------------------------------------------------
extern "C" void kernel_launch(void* const* d_in, const int* in_sizes, int n_in,
                              void* d_out, int out_size)
{
    const float* x       = (const float*)d_in[0];
    const float* edge_w  = (const float*)d_in[1];
    const float* W1      = (const float*)d_in[2];
    const float* b1      = (const float*)d_in[3];
    const float* W2      = (const float*)d_in[4];
    const float* b2      = (const float*)d_in[5];
    const float* W3      = (const float*)d_in[6];
    const float* b3      = (const float*)d_in[7];
    const float* linW    = (const float*)d_in[8];
    const float* linb    = (const float*)d_in[9];
    const int*   esrc    = (const int*)d_in[10];
    const int*   edst    = (const int*)d_in[11];
    float*       out     = (float*)d_out;

    static __nv_bfloat16 *supb = nullptr;
    static float *x1 = nullptr, *x2 = nullptr, *x3 = nullptr;
    static int *deg = nullptr, *cur = nullptr, *rp = nullptr, *csrc = nullptr;
    static float *cw = nullptr;
    static cudaStream_t s2 = nullptr;
    static cudaEvent_t evF = nullptr, evJ = nullptr;
    if (!supb) {
        cudaGetSymbolAddress((void**)&supb, g_supb);
        cudaGetSymbolAddress((void**)&x1,   g_x1);
        cudaGetSymbolAddress((void**)&x2,   g_x2);
        cudaGetSymbolAddress((void**)&x3,   g_x3);
        cudaGetSymbolAddress((void**)&deg,  g_deg);
        cudaGetSymbolAddress((void**)&cur,  g_cursor);
        cudaGetSymbolAddress((void**)&rp,   g_row_ptr);
        cudaGetSymbolAddress((void**)&csrc, g_csr_src);
        cudaGetSymbolAddress((void**)&cw,   g_csr_w);
        cudaStreamCreateWithFlags(&s2, cudaStreamNonBlocking);
        cudaEventCreateWithFlags(&evF, cudaEventDisableTiming);
        cudaEventCreateWithFlags(&evJ, cudaEventDisableTiming);
    }

    const int M = NN, E = EE;
    const int spmm_blocks = (M * 32 + 255) / 256;

    // ---- fork: CSR build on side stream, overlapped with GEMM-1 ----
    cudaEventRecord(evF, 0);
    cudaStreamWaitEvent(s2, evF, 0);
    zero_int2_kernel<<<(M + 255) / 256, 256, 0, s2>>>(deg, cur, M);
    degree_kernel<<<(E + 255) / 256, 256, 0, s2>>>(edst, deg, E);
    scan_kernel<<<1, 1024, 0, s2>>>(deg, rp, M);
    scatter_kernel<<<(E + 255) / 256, 256, 0, s2>>>(esrc, edst, edge_w, rp, cur, csrc, cw, E);
    cudaEventRecord(evJ, s2);

    // ---- layer 1 GEMM runs concurrently with CSR build ----
    {
        dim3 grid((M + 127) / 128, 256 / 64);
        bf16_gemm_kernel<<<grid, 256>>>(x, W1, supb, M, 512, 256);
    }
    cudaStreamWaitEvent(0, evJ, 0);   // join: SpMM needs CSR + support
    spmm_bf16_kernel<256, true><<<spmm_blocks, 256>>>(supb, rp, csrc, cw, b1, x1, M);

    // ---- layer 2 ----
    {
        dim3 grid((M + 127) / 128, 256 / 64);
        bf16_gemm_kernel<<<grid, 256>>>(x1, W2, supb, M, 256, 256);
        spmm_bf16_kernel<256, true><<<spmm_blocks, 256>>>(supb, rp, csrc, cw, b2, x2, M);
    }
    // ---- layer 3 (no relu) ----
    {
        dim3 grid((M + 127) / 128, 128 / 64);
        bf16_gemm_kernel<<<grid, 256>>>(x2, W3, supb, M, 256, 128);
        spmm_bf16_kernel<128, false><<<spmm_blocks, 256>>>(supb, rp, csrc, cw, b3, x3, M);
    }
    // ---- head ----
    head_kernel<<<(M * 16 + 255) / 256, 256>>>(x1, x2, x3, linW, linb, out, M);
}

// round 14
// speedup vs baseline: 2.6794x; 1.1445x over previous
#include <cuda_runtime.h>
#include <cuda_bf16.h>
#include <cstddef>
#include <cstdint>

#define NN 50000
#define EE 1600000

// ---------------- scratch (static device globals; no allocation allowed) ----
__device__ __align__(16) __nv_bfloat16 g_supb[(size_t)NN * 256];  // support, bf16
__device__ __align__(16) float g_x1[(size_t)NN * 256];
__device__ __align__(16) float g_x2[(size_t)NN * 256];
__device__ __align__(16) float g_x3[(size_t)NN * 128];

// CSR-by-destination scratch
__device__ int   g_deg[NN];
__device__ int   g_cursor[NN];
__device__ int   g_row_ptr[NN + 1];
__device__ int   g_csr_src[EE];
__device__ float g_csr_w[EE];

// ---------------- CSR build -------------------------------------------------
__global__ void zero_int2_kernel(int* __restrict__ a, int* __restrict__ b, int n) {
    int i = blockIdx.x * blockDim.x + threadIdx.x;
    if (i < n) { a[i] = 0; b[i] = 0; }
}

__global__ void degree_kernel(const int* __restrict__ dst, int* __restrict__ deg, int E) {
    int e = blockIdx.x * blockDim.x + threadIdx.x;
    if (e < E) atomicAdd(&deg[dst[e]], 1);
}

__global__ __launch_bounds__(1024) void scan_kernel(
    const int* __restrict__ deg, int* __restrict__ row_ptr, int n)
{
    __shared__ int ssum[1024];
    const int t  = threadIdx.x;
    const int CH = (n + 1023) / 1024;
    const int base = t * CH;

    int local = 0;
    for (int i = 0; i < CH; i++) {
        int idx = base + i;
        if (idx < n) local += deg[idx];
    }
    ssum[t] = local;
    __syncthreads();

    for (int off = 1; off < 1024; off <<= 1) {
        int add = (t >= off) ? ssum[t - off] : 0;
        __syncthreads();
        ssum[t] += add;
        __syncthreads();
    }

    int run = (t == 0) ? 0 : ssum[t - 1];
    for (int i = 0; i < CH; i++) {
        int idx = base + i;
        if (idx < n) { row_ptr[idx] = run; run += deg[idx]; }
    }
    if (t == 0) row_ptr[n] = ssum[1023];
}

__global__ void scatter_kernel(
    const int* __restrict__ src, const int* __restrict__ dst,
    const float* __restrict__ w,
    const int* __restrict__ row_ptr, int* __restrict__ cursor,
    int* __restrict__ csr_src, float* __restrict__ csr_w, int E)
{
    int e = blockIdx.x * blockDim.x + threadIdx.x;
    if (e >= E) return;
    int d   = dst[e];
    int pos = atomicAdd(&cursor[d], 1);
    int idx = row_ptr[d] + pos;
    csr_src[idx] = src[e];
    csr_w[idx]   = w[e];
}

// ---------------- tf32 tensor-core GEMM (m16n8k8, SINGLE pass), bf16 out ----
// C[M,N] = A[M,K] @ B[K,N], row-major fp32 in, bf16 out.
// tf32 rounding unit 2^-11: per-layer input-rounding rel err ~2.7e-4 RMS,
// 4x finer than bf16 (which measured 1.53e-3 end-to-end and failed).
__device__ __forceinline__ uint32_t f2tf32(float x) {
    uint32_t r;
    asm("cvt.rna.tf32.f32 %0, %1;" : "=r"(r) : "f"(x));
    return r;
}
__device__ __forceinline__ void mma_tf32(float c[4], const uint32_t a[4], const uint32_t b[2]) {
    asm volatile(
        "mma.sync.aligned.m16n8k8.row.col.f32.tf32.tf32.f32 "
        "{%0,%1,%2,%3}, {%4,%5,%6,%7}, {%8,%9}, {%0,%1,%2,%3};"
        : "+f"(c[0]), "+f"(c[1]), "+f"(c[2]), "+f"(c[3])
        : "r"(a[0]), "r"(a[1]), "r"(a[2]), "r"(a[3]), "r"(b[0]), "r"(b[1]));
}

__global__ __launch_bounds__(256) void tf32_gemm_kernel(
    const float* __restrict__ A, const float* __restrict__ B,
    __nv_bfloat16* __restrict__ C, int M, int K, int N)
{
    __shared__ float As[128][20];  // stride 20: conflict-free frag reads
    __shared__ float Bs[16][72];   // stride 72: conflict-free frag reads

    const int t    = threadIdx.x;
    const int wid  = t >> 5;
    const int lane = t & 31;
    const int wm   = (wid & 3) * 32;   // warp m offset in tile
    const int wn   = (wid >> 2) * 32;  // warp n offset in tile
    const int g    = lane >> 2;        // fragment group 0..7
    const int tg   = lane & 3;         // fragment thread-in-group 0..3

    const int m0 = blockIdx.x * 128;
    const int n0 = blockIdx.y * 64;

    const int ar = t >> 2;
    const int ac = (t & 3) * 4;
    const int br = t >> 4;
    const int bc = (t & 15) * 4;

    float c[2][4][4] = {};

    float4 aP0, aP1, bP;
    {
        const int gm0 = m0 + ar, gm1 = m0 + ar + 64;
        aP0 = (gm0 < M) ? *(const float4*)(A + (size_t)gm0 * K + ac) : make_float4(0,0,0,0);
        aP1 = (gm1 < M) ? *(const float4*)(A + (size_t)gm1 * K + ac) : make_float4(0,0,0,0);
        bP  = *(const float4*)(B + (size_t)br * N + n0 + bc);
    }

    for (int k0 = 0; k0 < K; k0 += 16) {
        *(float4*)&As[ar][ac]      = aP0;
        *(float4*)&As[ar + 64][ac] = aP1;
        *(float4*)&Bs[br][bc]      = bP;
        __syncthreads();

        if (k0 + 16 < K) {
            const int gm0 = m0 + ar, gm1 = m0 + ar + 64;
            const int kn = k0 + 16;
            aP0 = (gm0 < M) ? *(const float4*)(A + (size_t)gm0 * K + kn + ac) : make_float4(0,0,0,0);
            aP1 = (gm1 < M) ? *(const float4*)(A + (size_t)gm1 * K + kn + ac) : make_float4(0,0,0,0);
            bP  = *(const float4*)(B + (size_t)(kn + br) * N + n0 + bc);
        }

#pragma unroll
        for (int kk = 0; kk < 16; kk += 8) {
            // A fragments (2 m-tiles), single tf32 conversion
            uint32_t ah[2][4];
#pragma unroll
            for (int mt = 0; mt < 2; mt++) {
                const int r0 = wm + mt * 16 + g;
                ah[mt][0] = f2tf32(As[r0][kk + tg]);
                ah[mt][1] = f2tf32(As[r0 + 8][kk + tg]);
                ah[mt][2] = f2tf32(As[r0][kk + tg + 4]);
                ah[mt][3] = f2tf32(As[r0 + 8][kk + tg + 4]);
            }
            // B fragments (4 n-tiles)
            uint32_t bh[4][2];
#pragma unroll
            for (int nt = 0; nt < 4; nt++) {
                const int cn = wn + nt * 8 + g;
                bh[nt][0] = f2tf32(Bs[kk + tg][cn]);
                bh[nt][1] = f2tf32(Bs[kk + tg + 4][cn]);
            }
            // single mma pass
#pragma unroll
            for (int mt = 0; mt < 2; mt++)
#pragma unroll
                for (int nt = 0; nt < 4; nt++)
                    mma_tf32(c[mt][nt], ah[mt], bh[nt]);
        }
        __syncthreads();
    }

    // epilogue: round-to-nearest bf16, paired stores (col always even)
#pragma unroll
    for (int mt = 0; mt < 2; mt++)
#pragma unroll
        for (int nt = 0; nt < 4; nt++) {
            const int col = n0 + wn + nt * 8 + tg * 2;
            const int r0  = m0 + wm + mt * 16 + g;
            if (r0 < M)
                *(__nv_bfloat162*)(C + (size_t)r0 * N + col) =
                    __floats2bfloat162_rn(c[mt][nt][0], c[mt][nt][1]);
            if (r0 + 8 < M)
                *(__nv_bfloat162*)(C + (size_t)(r0 + 8) * N + col) =
                    __floats2bfloat162_rn(c[mt][nt][2], c[mt][nt][3]);
        }
}

// ---------------- CSR SpMM over bf16 support, fp32 accumulate ---------------
template<int F, bool RELU>
__global__ __launch_bounds__(256) void spmm_bf16_kernel(
    const __nv_bfloat16* __restrict__ sup,
    const int* __restrict__ row_ptr,
    const int* __restrict__ csr_src,
    const float* __restrict__ csr_w,
    const float* __restrict__ bias,
    float* __restrict__ out, int n)
{
    constexpr int PL = F / 32;          // floats per lane (8 or 4)
    const int gtid = blockIdx.x * blockDim.x + threadIdx.x;
    const int r    = gtid >> 5;
    const int lane = gtid & 31;
    if (r >= n) return;

    const int start = row_ptr[r];
    const int end   = row_ptr[r + 1];

    float acc[PL];
#pragma unroll
    for (int j = 0; j < PL; j++) acc[j] = 0.f;

    for (int base = start; base < end; base += 32) {
        const int cnt = min(32, end - base);
        int   s_l = 0;
        float w_l = 0.f;
        if (lane < cnt) {
            s_l = csr_src[base + lane];
            w_l = csr_w[base + lane];
        }
#pragma unroll 4
        for (int k = 0; k < cnt; k++) {
            const int   s = __shfl_sync(0xffffffffu, s_l, k);
            const float w = __shfl_sync(0xffffffffu, w_l, k);
            const __nv_bfloat16* __restrict__ row = sup + (size_t)s * F;
            if (F == 256) {
                const uint4 v = __ldg((const uint4*)row + lane);
                float2 f0 = __bfloat1622float2(*(const __nv_bfloat162*)&v.x);
                float2 f1 = __bfloat1622float2(*(const __nv_bfloat162*)&v.y);
                float2 f2 = __bfloat1622float2(*(const __nv_bfloat162*)&v.z);
                float2 f3 = __bfloat1622float2(*(const __nv_bfloat162*)&v.w);
                acc[0] = fmaf(w, f0.x, acc[0]); acc[1] = fmaf(w, f0.y, acc[1]);
                acc[2] = fmaf(w, f1.x, acc[2]); acc[3] = fmaf(w, f1.y, acc[3]);
                acc[4] = fmaf(w, f2.x, acc[4]); acc[5] = fmaf(w, f2.y, acc[5]);
                acc[6] = fmaf(w, f3.x, acc[6]); acc[7] = fmaf(w, f3.y, acc[7]);
            } else {
                const uint2 v = __ldg((const uint2*)row + lane);
                float2 f0 = __bfloat1622float2(*(const __nv_bfloat162*)&v.x);
                float2 f1 = __bfloat1622float2(*(const __nv_bfloat162*)&v.y);
                acc[0] = fmaf(w, f0.x, acc[0]); acc[1] = fmaf(w, f0.y, acc[1]);
                acc[2] = fmaf(w, f1.x, acc[2]); acc[3] = fmaf(w, f1.y, acc[3]);
            }
        }
    }

    const int c0 = lane * PL;
#pragma unroll
    for (int j = 0; j < PL; j++) {
        acc[j] += bias[c0 + j];
        if (RELU) acc[j] = fmaxf(acc[j], 0.f);
    }
    float* __restrict__ orow = out + (size_t)r * F + c0;
#pragma unroll
    for (int j = 0; j < PL; j += 4)
        *(float4*)(orow + j) = make_float4(acc[j], acc[j+1], acc[j+2], acc[j+3]);
}

// ---------------- head: concat(640) @ linW[640,16] + linb, log_softmax ------
__global__ __launch_bounds__(256) void head_kernel(
    const float* __restrict__ x1, const float* __restrict__ x2,
    const float* __restrict__ x3,
    const float* __restrict__ linW, const float* __restrict__ linb,
    float* __restrict__ out, int n)
{
    __shared__ float sW[640 * 16];
    for (int i = threadIdx.x; i < 640 * 16; i += blockDim.x) sW[i] = linW[i];
    __syncthreads();

    const int gtid = blockIdx.x * blockDim.x + threadIdx.x;
    const int node = gtid >> 4;
    const int c    = gtid & 15;
    if (node >= n) return;

    const float* __restrict__ r1 = x1 + (size_t)node * 256;
    const float* __restrict__ r2 = x2 + (size_t)node * 256;
    const float* __restrict__ r3 = x3 + (size_t)node * 128;

    float acc = linb[c];
#pragma unroll 4
    for (int k = 0; k < 256; k++) acc = fmaf(r1[k], sW[k * 16 + c], acc);
#pragma unroll 4
    for (int k = 0; k < 256; k++) acc = fmaf(r2[k], sW[(256 + k) * 16 + c], acc);
#pragma unroll 4
    for (int k = 0; k < 128; k++) acc = fmaf(r3[k], sW[(512 + k) * 16 + c], acc);

    float m = acc;
#pragma unroll
    for (int o = 8; o > 0; o >>= 1)
        m = fmaxf(m, __shfl_xor_sync(0xffffffffu, m, o));
    float ex = expf(acc - m);
    float ssum = ex;
#pragma unroll
    for (int o = 8; o > 0; o >>= 1)
        ssum += __shfl_xor_sync(0xffffffffu, ssum, o);

    out[(size_t)node * 16 + c] = acc - m - logf(ssum);
}

// ---------------- launch ----------------------------------------------------
extern "C" void kernel_launch(void* const* d_in, const int* in_sizes, int n_in,
                              void* d_out, int out_size)
{
    const float* x       = (const float*)d_in[0];
    const float* edge_w  = (const float*)d_in[1];
    const float* W1      = (const float*)d_in[2];
    const float* b1      = (const float*)d_in[3];
    const float* W2      = (const float*)d_in[4];
    const float* b2      = (const float*)d_in[5];
    const float* W3      = (const float*)d_in[6];
    const float* b3      = (const float*)d_in[7];
    const float* linW    = (const float*)d_in[8];
    const float* linb    = (const float*)d_in[9];
    const int*   esrc    = (const int*)d_in[10];
    const int*   edst    = (const int*)d_in[11];
    float*       out     = (float*)d_out;

    static __nv_bfloat16 *supb = nullptr;
    static float *x1 = nullptr, *x2 = nullptr, *x3 = nullptr;
    static int *deg = nullptr, *cur = nullptr, *rp = nullptr, *csrc = nullptr;
    static float *cw = nullptr;
    static cudaStream_t s2 = nullptr;
    static cudaEvent_t evF = nullptr, evJ = nullptr;
    if (!supb) {
        cudaGetSymbolAddress((void**)&supb, g_supb);
        cudaGetSymbolAddress((void**)&x1,   g_x1);
        cudaGetSymbolAddress((void**)&x2,   g_x2);
        cudaGetSymbolAddress((void**)&x3,   g_x3);
        cudaGetSymbolAddress((void**)&deg,  g_deg);
        cudaGetSymbolAddress((void**)&cur,  g_cursor);
        cudaGetSymbolAddress((void**)&rp,   g_row_ptr);
        cudaGetSymbolAddress((void**)&csrc, g_csr_src);
        cudaGetSymbolAddress((void**)&cw,   g_csr_w);
        cudaStreamCreateWithFlags(&s2, cudaStreamNonBlocking);
        cudaEventCreateWithFlags(&evF, cudaEventDisableTiming);
        cudaEventCreateWithFlags(&evJ, cudaEventDisableTiming);
    }

    const int M = NN, E = EE;
    const int spmm_blocks = (M * 32 + 255) / 256;

    // ---- fork: CSR build on side stream, overlapped with GEMM-1 ----
    cudaEventRecord(evF, 0);
    cudaStreamWaitEvent(s2, evF, 0);
    zero_int2_kernel<<<(M + 255) / 256, 256, 0, s2>>>(deg, cur, M);
    degree_kernel<<<(E + 255) / 256, 256, 0, s2>>>(edst, deg, E);
    scan_kernel<<<1, 1024, 0, s2>>>(deg, rp, M);
    scatter_kernel<<<(E + 255) / 256, 256, 0, s2>>>(esrc, edst, edge_w, rp, cur, csrc, cw, E);
    cudaEventRecord(evJ, s2);

    // ---- layer 1: support = bf16(x @ W1), overlapped with CSR build ----
    {
        dim3 grid((M + 127) / 128, 256 / 64);
        tf32_gemm_kernel<<<grid, 256>>>(x, W1, supb, M, 512, 256);
    }
    cudaStreamWaitEvent(0, evJ, 0);   // join: SpMM needs CSR + support
    spmm_bf16_kernel<256, true><<<spmm_blocks, 256>>>(supb, rp, csrc, cw, b1, x1, M);

    // ---- layer 2 ----
    {
        dim3 grid((M + 127) / 128, 256 / 64);
        tf32_gemm_kernel<<<grid, 256>>>(x1, W2, supb, M, 256, 256);
        spmm_bf16_kernel<256, true><<<spmm_blocks, 256>>>(supb, rp, csrc, cw, b2, x2, M);
    }
    // ---- layer 3 (no relu) ----
    {
        dim3 grid((M + 127) / 128, 128 / 64);
        tf32_gemm_kernel<<<grid, 256>>>(x2, W3, supb, M, 256, 128);
        spmm_bf16_kernel<128, false><<<spmm_blocks, 256>>>(supb, rp, csrc, cw, b3, x3, M);
    }
    // ---- head ----
    head_kernel<<<(M * 16 + 255) / 256, 256>>>(x1, x2, x3, linW, linb, out, M);
}

// round 15
// speedup vs baseline: 2.7444x; 1.0243x over previous
#include <cuda_runtime.h>
#include <cuda_bf16.h>
#include <cstddef>
#include <cstdint>

#define NN 50000
#define EE 1600000

// ---------------- scratch (static device globals; no allocation allowed) ----
__device__ __align__(16) __nv_bfloat16 g_supb[(size_t)NN * 256];  // support, bf16
__device__ __align__(16) float g_x1[(size_t)NN * 256];
__device__ __align__(16) float g_x2[(size_t)NN * 256];
__device__ __align__(16) float g_x3[(size_t)NN * 128];

// CSR-by-destination scratch
__device__ int   g_deg[NN];
__device__ int   g_cursor[NN];
__device__ int   g_row_ptr[NN + 1];
__device__ int   g_csr_src[EE];
__device__ float g_csr_w[EE];

// ---------------- CSR build -------------------------------------------------
__global__ void zero_int2_kernel(int* __restrict__ a, int* __restrict__ b, int n) {
    int i = blockIdx.x * blockDim.x + threadIdx.x;
    if (i < n) { a[i] = 0; b[i] = 0; }
}

__global__ void degree_kernel(const int* __restrict__ dst, int* __restrict__ deg, int E) {
    int e = blockIdx.x * blockDim.x + threadIdx.x;
    if (e < E) atomicAdd(&deg[dst[e]], 1);
}

__global__ __launch_bounds__(1024) void scan_kernel(
    const int* __restrict__ deg, int* __restrict__ row_ptr, int n)
{
    __shared__ int ssum[1024];
    const int t  = threadIdx.x;
    const int CH = (n + 1023) / 1024;
    const int base = t * CH;

    int local = 0;
    for (int i = 0; i < CH; i++) {
        int idx = base + i;
        if (idx < n) local += deg[idx];
    }
    ssum[t] = local;
    __syncthreads();

    for (int off = 1; off < 1024; off <<= 1) {
        int add = (t >= off) ? ssum[t - off] : 0;
        __syncthreads();
        ssum[t] += add;
        __syncthreads();
    }

    int run = (t == 0) ? 0 : ssum[t - 1];
    for (int i = 0; i < CH; i++) {
        int idx = base + i;
        if (idx < n) { row_ptr[idx] = run; run += deg[idx]; }
    }
    if (t == 0) row_ptr[n] = ssum[1023];
}

__global__ void scatter_kernel(
    const int* __restrict__ src, const int* __restrict__ dst,
    const float* __restrict__ w,
    const int* __restrict__ row_ptr, int* __restrict__ cursor,
    int* __restrict__ csr_src, float* __restrict__ csr_w, int E)
{
    int e = blockIdx.x * blockDim.x + threadIdx.x;
    if (e >= E) return;
    int d   = dst[e];
    int pos = atomicAdd(&cursor[d], 1);
    int idx = row_ptr[d] + pos;
    csr_src[idx] = src[e];
    csr_w[idx]   = w[e];
}

// ---------------- tf32 tensor-core GEMM (m16n8k8, SINGLE pass), bf16 out ----
__device__ __forceinline__ uint32_t f2tf32(float x) {
    uint32_t r;
    asm("cvt.rna.tf32.f32 %0, %1;" : "=r"(r) : "f"(x));
    return r;
}
__device__ __forceinline__ void mma_tf32(float c[4], const uint32_t a[4], const uint32_t b[2]) {
    asm volatile(
        "mma.sync.aligned.m16n8k8.row.col.f32.tf32.tf32.f32 "
        "{%0,%1,%2,%3}, {%4,%5,%6,%7}, {%8,%9}, {%0,%1,%2,%3};"
        : "+f"(c[0]), "+f"(c[1]), "+f"(c[2]), "+f"(c[3])
        : "r"(a[0]), "r"(a[1]), "r"(a[2]), "r"(a[3]), "r"(b[0]), "r"(b[1]));
}

__global__ __launch_bounds__(256) void tf32_gemm_kernel(
    const float* __restrict__ A, const float* __restrict__ B,
    __nv_bfloat16* __restrict__ C, int M, int K, int N)
{
    __shared__ float As[128][20];
    __shared__ float Bs[16][72];

    const int t    = threadIdx.x;
    const int wid  = t >> 5;
    const int lane = t & 31;
    const int wm   = (wid & 3) * 32;
    const int wn   = (wid >> 2) * 32;
    const int g    = lane >> 2;
    const int tg   = lane & 3;

    const int m0 = blockIdx.x * 128;
    const int n0 = blockIdx.y * 64;

    const int ar = t >> 2;
    const int ac = (t & 3) * 4;
    const int br = t >> 4;
    const int bc = (t & 15) * 4;

    float c[2][4][4] = {};

    float4 aP0, aP1, bP;
    {
        const int gm0 = m0 + ar, gm1 = m0 + ar + 64;
        aP0 = (gm0 < M) ? *(const float4*)(A + (size_t)gm0 * K + ac) : make_float4(0,0,0,0);
        aP1 = (gm1 < M) ? *(const float4*)(A + (size_t)gm1 * K + ac) : make_float4(0,0,0,0);
        bP  = *(const float4*)(B + (size_t)br * N + n0 + bc);
    }

    for (int k0 = 0; k0 < K; k0 += 16) {
        *(float4*)&As[ar][ac]      = aP0;
        *(float4*)&As[ar + 64][ac] = aP1;
        *(float4*)&Bs[br][bc]      = bP;
        __syncthreads();

        if (k0 + 16 < K) {
            const int gm0 = m0 + ar, gm1 = m0 + ar + 64;
            const int kn = k0 + 16;
            aP0 = (gm0 < M) ? *(const float4*)(A + (size_t)gm0 * K + kn + ac) : make_float4(0,0,0,0);
            aP1 = (gm1 < M) ? *(const float4*)(A + (size_t)gm1 * K + kn + ac) : make_float4(0,0,0,0);
            bP  = *(const float4*)(B + (size_t)(kn + br) * N + n0 + bc);
        }

#pragma unroll
        for (int kk = 0; kk < 16; kk += 8) {
            uint32_t ah[2][4];
#pragma unroll
            for (int mt = 0; mt < 2; mt++) {
                const int r0 = wm + mt * 16 + g;
                ah[mt][0] = f2tf32(As[r0][kk + tg]);
                ah[mt][1] = f2tf32(As[r0 + 8][kk + tg]);
                ah[mt][2] = f2tf32(As[r0][kk + tg + 4]);
                ah[mt][3] = f2tf32(As[r0 + 8][kk + tg + 4]);
            }
            uint32_t bh[4][2];
#pragma unroll
            for (int nt = 0; nt < 4; nt++) {
                const int cn = wn + nt * 8 + g;
                bh[nt][0] = f2tf32(Bs[kk + tg][cn]);
                bh[nt][1] = f2tf32(Bs[kk + tg + 4][cn]);
            }
#pragma unroll
            for (int mt = 0; mt < 2; mt++)
#pragma unroll
                for (int nt = 0; nt < 4; nt++)
                    mma_tf32(c[mt][nt], ah[mt], bh[nt]);
        }
        __syncthreads();
    }

#pragma unroll
    for (int mt = 0; mt < 2; mt++)
#pragma unroll
        for (int nt = 0; nt < 4; nt++) {
            const int col = n0 + wn + nt * 8 + tg * 2;
            const int r0  = m0 + wm + mt * 16 + g;
            if (r0 < M)
                *(__nv_bfloat162*)(C + (size_t)r0 * N + col) =
                    __floats2bfloat162_rn(c[mt][nt][0], c[mt][nt][1]);
            if (r0 + 8 < M)
                *(__nv_bfloat162*)(C + (size_t)(r0 + 8) * N + col) =
                    __floats2bfloat162_rn(c[mt][nt][2], c[mt][nt][3]);
        }
}

// ---------------- CSR SpMM over bf16 support, fp32 accumulate ---------------
// Explicit 8-edge batching: 8 independent gathers in flight (MLP=8) before
// any FMA consumes them — the inner loop was latency-bound at MLP~4.
template<int F, bool RELU>
__global__ __launch_bounds__(256) void spmm_bf16_kernel(
    const __nv_bfloat16* __restrict__ sup,
    const int* __restrict__ row_ptr,
    const int* __restrict__ csr_src,
    const float* __restrict__ csr_w,
    const float* __restrict__ bias,
    float* __restrict__ out, int n)
{
    constexpr int PL = F / 32;          // floats per lane (8 or 4)
    const int gtid = blockIdx.x * blockDim.x + threadIdx.x;
    const int r    = gtid >> 5;
    const int lane = gtid & 31;
    if (r >= n) return;

    const int start = row_ptr[r];
    const int end   = row_ptr[r + 1];

    float acc[PL];
#pragma unroll
    for (int j = 0; j < PL; j++) acc[j] = 0.f;

    for (int base = start; base < end; base += 32) {
        const int cnt = min(32, end - base);
        int   s_l = 0;
        float w_l = 0.f;
        if (lane < cnt) {
            s_l = csr_src[base + lane];
            w_l = csr_w[base + lane];
        }

        int k = 0;
        // ---- 8-edge batches: issue all 8 gathers, then all FMAs ----
        for (; k + 8 <= cnt; k += 8) {
            float we[8];
            if (F == 256) {
                uint4 v[8];
#pragma unroll
                for (int j = 0; j < 8; j++) {
                    const int s = __shfl_sync(0xffffffffu, s_l, k + j);
                    we[j] = __shfl_sync(0xffffffffu, w_l, k + j);
                    v[j] = __ldg((const uint4*)(sup + (size_t)s * F) + lane);
                }
#pragma unroll
                for (int j = 0; j < 8; j++) {
                    const float w = we[j];
                    float2 f0 = __bfloat1622float2(*(const __nv_bfloat162*)&v[j].x);
                    float2 f1 = __bfloat1622float2(*(const __nv_bfloat162*)&v[j].y);
                    float2 f2 = __bfloat1622float2(*(const __nv_bfloat162*)&v[j].z);
                    float2 f3 = __bfloat1622float2(*(const __nv_bfloat162*)&v[j].w);
                    acc[0] = fmaf(w, f0.x, acc[0]); acc[1] = fmaf(w, f0.y, acc[1]);
                    acc[2] = fmaf(w, f1.x, acc[2]); acc[3] = fmaf(w, f1.y, acc[3]);
                    acc[4] = fmaf(w, f2.x, acc[4]); acc[5] = fmaf(w, f2.y, acc[5]);
                    acc[6] = fmaf(w, f3.x, acc[6]); acc[7] = fmaf(w, f3.y, acc[7]);
                }
            } else {
                uint2 v[8];
#pragma unroll
                for (int j = 0; j < 8; j++) {
                    const int s = __shfl_sync(0xffffffffu, s_l, k + j);
                    we[j] = __shfl_sync(0xffffffffu, w_l, k + j);
                    v[j] = __ldg((const uint2*)(sup + (size_t)s * F) + lane);
                }
#pragma unroll
                for (int j = 0; j < 8; j++) {
                    const float w = we[j];
                    float2 f0 = __bfloat1622float2(*(const __nv_bfloat162*)&v[j].x);
                    float2 f1 = __bfloat1622float2(*(const __nv_bfloat162*)&v[j].y);
                    acc[0] = fmaf(w, f0.x, acc[0]); acc[1] = fmaf(w, f0.y, acc[1]);
                    acc[2] = fmaf(w, f1.x, acc[2]); acc[3] = fmaf(w, f1.y, acc[3]);
                }
            }
        }
        // ---- remainder edges ----
        for (; k < cnt; k++) {
            const int   s = __shfl_sync(0xffffffffu, s_l, k);
            const float w = __shfl_sync(0xffffffffu, w_l, k);
            const __nv_bfloat16* __restrict__ row = sup + (size_t)s * F;
            if (F == 256) {
                const uint4 v = __ldg((const uint4*)row + lane);
                float2 f0 = __bfloat1622float2(*(const __nv_bfloat162*)&v.x);
                float2 f1 = __bfloat1622float2(*(const __nv_bfloat162*)&v.y);
                float2 f2 = __bfloat1622float2(*(const __nv_bfloat162*)&v.z);
                float2 f3 = __bfloat1622float2(*(const __nv_bfloat162*)&v.w);
                acc[0] = fmaf(w, f0.x, acc[0]); acc[1] = fmaf(w, f0.y, acc[1]);
                acc[2] = fmaf(w, f1.x, acc[2]); acc[3] = fmaf(w, f1.y, acc[3]);
                acc[4] = fmaf(w, f2.x, acc[4]); acc[5] = fmaf(w, f2.y, acc[5]);
                acc[6] = fmaf(w, f3.x, acc[6]); acc[7] = fmaf(w, f3.y, acc[7]);
            } else {
                const uint2 v = __ldg((const uint2*)row + lane);
                float2 f0 = __bfloat1622float2(*(const __nv_bfloat162*)&v.x);
                float2 f1 = __bfloat1622float2(*(const __nv_bfloat162*)&v.y);
                acc[0] = fmaf(w, f0.x, acc[0]); acc[1] = fmaf(w, f0.y, acc[1]);
                acc[2] = fmaf(w, f1.x, acc[2]); acc[3] = fmaf(w, f1.y, acc[3]);
            }
        }
    }

    const int c0 = lane * PL;
#pragma unroll
    for (int j = 0; j < PL; j++) {
        acc[j] += bias[c0 + j];
        if (RELU) acc[j] = fmaxf(acc[j], 0.f);
    }
    float* __restrict__ orow = out + (size_t)r * F + c0;
#pragma unroll
    for (int j = 0; j < PL; j += 4)
        *(float4*)(orow + j) = make_float4(acc[j], acc[j+1], acc[j+2], acc[j+3]);
}

// ---------------- head: concat(640) @ linW[640,16] + linb, log_softmax ------
__global__ __launch_bounds__(256) void head_kernel(
    const float* __restrict__ x1, const float* __restrict__ x2,
    const float* __restrict__ x3,
    const float* __restrict__ linW, const float* __restrict__ linb,
    float* __restrict__ out, int n)
{
    __shared__ float sW[640 * 16];
    for (int i = threadIdx.x; i < 640 * 16; i += blockDim.x) sW[i] = linW[i];
    __syncthreads();

    const int gtid = blockIdx.x * blockDim.x + threadIdx.x;
    const int node = gtid >> 4;
    const int c    = gtid & 15;
    if (node >= n) return;

    const float* __restrict__ r1 = x1 + (size_t)node * 256;
    const float* __restrict__ r2 = x2 + (size_t)node * 256;
    const float* __restrict__ r3 = x3 + (size_t)node * 128;

    float acc = linb[c];
#pragma unroll 4
    for (int k = 0; k < 256; k++) acc = fmaf(r1[k], sW[k * 16 + c], acc);
#pragma unroll 4
    for (int k = 0; k < 256; k++) acc = fmaf(r2[k], sW[(256 + k) * 16 + c], acc);
#pragma unroll 4
    for (int k = 0; k < 128; k++) acc = fmaf(r3[k], sW[(512 + k) * 16 + c], acc);

    float m = acc;
#pragma unroll
    for (int o = 8; o > 0; o >>= 1)
        m = fmaxf(m, __shfl_xor_sync(0xffffffffu, m, o));
    float ex = expf(acc - m);
    float ssum = ex;
#pragma unroll
    for (int o = 8; o > 0; o >>= 1)
        ssum += __shfl_xor_sync(0xffffffffu, ssum, o);

    out[(size_t)node * 16 + c] = acc - m - logf(ssum);
}

// ---------------- launch ----------------------------------------------------
extern "C" void kernel_launch(void* const* d_in, const int* in_sizes, int n_in,
                              void* d_out, int out_size)
{
    const float* x       = (const float*)d_in[0];
    const float* edge_w  = (const float*)d_in[1];
    const float* W1      = (const float*)d_in[2];
    const float* b1      = (const float*)d_in[3];
    const float* W2      = (const float*)d_in[4];
    const float* b2      = (const float*)d_in[5];
    const float* W3      = (const float*)d_in[6];
    const float* b3      = (const float*)d_in[7];
    const float* linW    = (const float*)d_in[8];
    const float* linb    = (const float*)d_in[9];
    const int*   esrc    = (const int*)d_in[10];
    const int*   edst    = (const int*)d_in[11];
    float*       out     = (float*)d_out;

    static __nv_bfloat16 *supb = nullptr;
    static float *x1 = nullptr, *x2 = nullptr, *x3 = nullptr;
    static int *deg = nullptr, *cur = nullptr, *rp = nullptr, *csrc = nullptr;
    static float *cw = nullptr;
    static cudaStream_t s2 = nullptr;
    static cudaEvent_t evF = nullptr, evJ = nullptr;
    if (!supb) {
        cudaGetSymbolAddress((void**)&supb, g_supb);
        cudaGetSymbolAddress((void**)&x1,   g_x1);
        cudaGetSymbolAddress((void**)&x2,   g_x2);
        cudaGetSymbolAddress((void**)&x3,   g_x3);
        cudaGetSymbolAddress((void**)&deg,  g_deg);
        cudaGetSymbolAddress((void**)&cur,  g_cursor);
        cudaGetSymbolAddress((void**)&rp,   g_row_ptr);
        cudaGetSymbolAddress((void**)&csrc, g_csr_src);
        cudaGetSymbolAddress((void**)&cw,   g_csr_w);
        cudaStreamCreateWithFlags(&s2, cudaStreamNonBlocking);
        cudaEventCreateWithFlags(&evF, cudaEventDisableTiming);
        cudaEventCreateWithFlags(&evJ, cudaEventDisableTiming);
    }

    const int M = NN, E = EE;
    const int spmm_blocks = (M * 32 + 255) / 256;

    // ---- fork: CSR build on side stream, overlapped with GEMM-1 ----
    cudaEventRecord(evF, 0);
    cudaStreamWaitEvent(s2, evF, 0);
    zero_int2_kernel<<<(M + 255) / 256, 256, 0, s2>>>(deg, cur, M);
    degree_kernel<<<(E + 255) / 256, 256, 0, s2>>>(edst, deg, E);
    scan_kernel<<<1, 1024, 0, s2>>>(deg, rp, M);
    scatter_kernel<<<(E + 255) / 256, 256, 0, s2>>>(esrc, edst, edge_w, rp, cur, csrc, cw, E);
    cudaEventRecord(evJ, s2);

    // ---- layer 1: support = bf16(x @ W1), overlapped with CSR build ----
    {
        dim3 grid((M + 127) / 128, 256 / 64);
        tf32_gemm_kernel<<<grid, 256>>>(x, W1, supb, M, 512, 256);
    }
    cudaStreamWaitEvent(0, evJ, 0);   // join: SpMM needs CSR + support
    spmm_bf16_kernel<256, true><<<spmm_blocks, 256>>>(supb, rp, csrc, cw, b1, x1, M);

    // ---- layer 2 ----
    {
        dim3 grid((M + 127) / 128, 256 / 64);
        tf32_gemm_kernel<<<grid, 256>>>(x1, W2, supb, M, 256, 256);
        spmm_bf16_kernel<256, true><<<spmm_blocks, 256>>>(supb, rp, csrc, cw, b2, x2, M);
    }
    // ---- layer 3 (no relu) ----
    {
        dim3 grid((M + 127) / 128, 128 / 64);
        tf32_gemm_kernel<<<grid, 256>>>(x2, W3, supb, M, 256, 128);
        spmm_bf16_kernel<128, false><<<spmm_blocks, 256>>>(supb, rp, csrc, cw, b3, x3, M);
    }
    // ---- head ----
    head_kernel<<<(M * 16 + 255) / 256, 256>>>(x1, x2, x3, linW, linb, out, M);
}